// round 1
// baseline (speedup 1.0000x reference)
#include <cuda_runtime.h>
#include <math.h>

#define BB 2
#define NN 16384
#define MM 4096
#define DD 128
#define SCALE 0.08838834764831845f   // 1/sqrt(128)

// ---------------- scratch (device globals: no allocations allowed) ----------
__device__ float g_scores[(size_t)BB * MM * NN];   // 512 MB
__device__ float g_kpv[BB * NN * DD];
__device__ float g_v[BB * NN * DD];
__device__ float g_q[BB * MM * DD];
__device__ float g_cmax[BB * NN];
__device__ float g_cinv[BB * NN];

// ---------------------------------------------------------------------------
// Shared GEMM phase: acc[4][8] += sT(kmajor,[128][65]) x W(chunked via wch)
// Thread map: tx = tid&15 -> 8 contiguous cols (tx*8..+7), ty = tid>>4 ->
// rows ty, ty+16, ty+32, ty+48 (strided => conflict-free sT column reads).
// ---------------------------------------------------------------------------
__device__ __forceinline__ void mlp_phase(const float* __restrict__ sT,
                                          float* wch,
                                          const float* __restrict__ W,
                                          float acc[4][8],
                                          int tx, int ty, int tid)
{
    #pragma unroll 1
    for (int kc = 0; kc < 4; ++kc) {
        for (int idx = tid; idx < 32 * 128; idx += 256)
            wch[idx] = W[kc * 32 * 128 + idx];
        __syncthreads();
        #pragma unroll
        for (int dd = 0; dd < 32; ++dd) {
            float a[4];
            #pragma unroll
            for (int i = 0; i < 4; ++i)
                a[i] = sT[(kc * 32 + dd) * 65 + ty + 16 * i];
            float4 w0 = *(const float4*)&wch[dd * 128 + tx * 8];
            float4 w1 = *(const float4*)&wch[dd * 128 + tx * 8 + 4];
            #pragma unroll
            for (int i = 0; i < 4; ++i) {
                acc[i][0] += a[i] * w0.x; acc[i][1] += a[i] * w0.y;
                acc[i][2] += a[i] * w0.z; acc[i][3] += a[i] * w0.w;
                acc[i][4] += a[i] * w1.x; acc[i][5] += a[i] * w1.y;
                acc[i][6] += a[i] * w1.z; acc[i][7] += a[i] * w1.w;
            }
        }
        __syncthreads();
    }
}

// ---------------------------------------------------------------------------
// Fused 2-layer MLP, din = 128.  64 rows per block, 256 threads.
// smem: sT [128][65] (input transposed, then reused for hidden transposed)
//       wch [32][128] weight chunk.  Total 49664 B (dynamic).
// ---------------------------------------------------------------------------
extern "C" __global__ void __launch_bounds__(256)
mlp128_kernel(const float* __restrict__ x,
              const float* __restrict__ W1, const float* __restrict__ b1,
              const float* __restrict__ W2, const float* __restrict__ b2,
              float* __restrict__ out, int addOut)
{
    extern __shared__ float smem[];
    float* sT  = smem;             // [128][65]
    float* wch = smem + 128 * 65;  // [32][128]
    int tid = threadIdx.x, tx = tid & 15, ty = tid >> 4;
    int row0 = blockIdx.x * 64;

    for (int idx = tid; idx < 64 * 128; idx += 256) {
        int r = idx >> 7, d = idx & 127;
        sT[d * 65 + r] = x[(size_t)(row0 + r) * 128 + d];
    }
    __syncthreads();

    float acc[4][8];
    #pragma unroll
    for (int i = 0; i < 4; ++i)
        #pragma unroll
        for (int j = 0; j < 8; ++j) acc[i][j] = 0.f;

    mlp_phase(sT, wch, W1, acc, tx, ty, tid);

    float bb[8];
    #pragma unroll
    for (int j = 0; j < 8; ++j) bb[j] = b1[tx * 8 + j];
    #pragma unroll
    for (int i = 0; i < 4; ++i)
        #pragma unroll
        for (int j = 0; j < 8; ++j) {
            float h = acc[i][j] + bb[j];
            sT[(tx * 8 + j) * 65 + ty + 16 * i] = h > 0.f ? h : 0.f;
            acc[i][j] = 0.f;
        }
    __syncthreads();

    mlp_phase(sT, wch, W2, acc, tx, ty, tid);

    #pragma unroll
    for (int j = 0; j < 8; ++j) bb[j] = b2[tx * 8 + j];
    #pragma unroll
    for (int i = 0; i < 4; ++i) {
        size_t o = (size_t)(row0 + ty + 16 * i) * 128 + tx * 8;
        float4 v0 = make_float4(acc[i][0] + bb[0], acc[i][1] + bb[1],
                                acc[i][2] + bb[2], acc[i][3] + bb[3]);
        float4 v1 = make_float4(acc[i][4] + bb[4], acc[i][5] + bb[5],
                                acc[i][6] + bb[6], acc[i][7] + bb[7]);
        if (addOut) {
            float4 o0 = *(float4*)&out[o];
            float4 o1 = *(float4*)&out[o + 4];
            v0.x += o0.x; v0.y += o0.y; v0.z += o0.z; v0.w += o0.w;
            v1.x += o1.x; v1.y += o1.y; v1.z += o1.z; v1.w += o1.w;
        }
        *(float4*)&out[o]     = v0;
        *(float4*)&out[o + 4] = v1;
    }
}

// ---------------------------------------------------------------------------
// delta MLP: dist = |p_xyz - v_xyz| (din=3) -> 128 -> 128. Writes kpv.
// smem: sT [128][65] + wch [32][128] + ds [64][4] + w1s [3][128] = 52224 B.
// ---------------------------------------------------------------------------
extern "C" __global__ void __launch_bounds__(256)
delta_mlp_kernel(const float* __restrict__ pxyz, const float* __restrict__ vxyz,
                 const float* __restrict__ W1, const float* __restrict__ b1,
                 const float* __restrict__ W2, const float* __restrict__ b2,
                 float* __restrict__ out)
{
    extern __shared__ float smem[];
    float* sT  = smem;                 // [128][65]
    float* wch = smem + 128 * 65;      // [32][128]
    float* ds  = wch + 32 * 128;       // [64][4]
    float* w1s = ds + 64 * 4;          // [3][128]
    int tid = threadIdx.x, tx = tid & 15, ty = tid >> 4;
    int row0 = blockIdx.x * 64;

    if (tid < 192) {
        int r = tid / 3, c = tid % 3;
        int gr = row0 + r;
        int b = gr >> 14;  // N = 16384
        ds[r * 4 + c] = fabsf(pxyz[(size_t)gr * 3 + c] - vxyz[b * 3 + c]);
    }
    for (int idx = tid; idx < 384; idx += 256) w1s[idx] = W1[idx];
    __syncthreads();

    for (int idx = tid; idx < 64 * 128; idx += 256) {
        int r = idx & 63, j = idx >> 6;
        float h = ds[r * 4] * w1s[j] + ds[r * 4 + 1] * w1s[128 + j] +
                  ds[r * 4 + 2] * w1s[256 + j] + b1[j];
        sT[j * 65 + r] = h > 0.f ? h : 0.f;
    }
    __syncthreads();

    float acc[4][8];
    #pragma unroll
    for (int i = 0; i < 4; ++i)
        #pragma unroll
        for (int j = 0; j < 8; ++j) acc[i][j] = 0.f;

    mlp_phase(sT, wch, W2, acc, tx, ty, tid);

    float bb[8];
    #pragma unroll
    for (int j = 0; j < 8; ++j) bb[j] = b2[tx * 8 + j];
    #pragma unroll
    for (int i = 0; i < 4; ++i) {
        size_t o = (size_t)(row0 + ty + 16 * i) * 128 + tx * 8;
        float4 v0 = make_float4(acc[i][0] + bb[0], acc[i][1] + bb[1],
                                acc[i][2] + bb[2], acc[i][3] + bb[3]);
        float4 v1 = make_float4(acc[i][4] + bb[4], acc[i][5] + bb[5],
                                acc[i][6] + bb[6], acc[i][7] + bb[7]);
        *(float4*)&out[o]     = v0;
        *(float4*)&out[o + 4] = v1;
    }
}

// ---------------------------------------------------------------------------
// Scores: S[b,m,n] = SCALE * sum_d q[b,m,d]*kpv[b,n,d]. 128x128 tile, K=128.
// 256 threads, 8x8 micro-tile per thread (cols contiguous -> float4 stores).
// ---------------------------------------------------------------------------
extern "C" __global__ void __launch_bounds__(256)
scores_kernel(const float* __restrict__ q, const float* __restrict__ kpv,
              float* __restrict__ S)
{
    __shared__ float qsT[32 * 132];
    __shared__ float ksT[32 * 132];
    int tid = threadIdx.x, tx = tid & 15, ty = tid >> 4;
    int n0 = blockIdx.x * 128, m0 = blockIdx.y * 128, b = blockIdx.z;
    const float* qb = q   + (size_t)(b * MM + m0) * 128;
    const float* kb = kpv + (size_t)(b * NN + n0) * 128;

    float acc[8][8];
    #pragma unroll
    for (int i = 0; i < 8; ++i)
        #pragma unroll
        for (int j = 0; j < 8; ++j) acc[i][j] = 0.f;

    #pragma unroll 1
    for (int kc = 0; kc < 4; ++kc) {
        __syncthreads();
        for (int idx = tid; idx < 128 * 32; idx += 256) {
            int r = idx >> 5, d = idx & 31;
            qsT[d * 132 + r] = qb[(size_t)r * 128 + kc * 32 + d];
            ksT[d * 132 + r] = kb[(size_t)r * 128 + kc * 32 + d];
        }
        __syncthreads();
        #pragma unroll
        for (int dd = 0; dd < 32; ++dd) {
            float a[8];
            #pragma unroll
            for (int i = 0; i < 8; ++i)
                a[i] = qsT[dd * 132 + ty + 16 * i];
            float4 k0 = *(float4*)&ksT[dd * 132 + tx * 8];
            float4 k1 = *(float4*)&ksT[dd * 132 + tx * 8 + 4];
            #pragma unroll
            for (int i = 0; i < 8; ++i) {
                acc[i][0] += a[i] * k0.x; acc[i][1] += a[i] * k0.y;
                acc[i][2] += a[i] * k0.z; acc[i][3] += a[i] * k0.w;
                acc[i][4] += a[i] * k1.x; acc[i][5] += a[i] * k1.y;
                acc[i][6] += a[i] * k1.z; acc[i][7] += a[i] * k1.w;
            }
        }
    }

    #pragma unroll
    for (int i = 0; i < 8; ++i) {
        size_t off = ((size_t)(b * MM + m0 + ty + 16 * i)) * NN + n0 + tx * 8;
        float4 v0 = make_float4(acc[i][0] * SCALE, acc[i][1] * SCALE,
                                acc[i][2] * SCALE, acc[i][3] * SCALE);
        float4 v1 = make_float4(acc[i][4] * SCALE, acc[i][5] * SCALE,
                                acc[i][6] * SCALE, acc[i][7] * SCALE);
        *(float4*)&S[off]     = v0;
        *(float4*)&S[off + 4] = v1;
    }
}

// ---------------------------------------------------------------------------
// Column softmax stats over m (axis=-2): online max+sum per column n.
// Block = 64 columns x 4 row-groups.
// ---------------------------------------------------------------------------
extern "C" __global__ void __launch_bounds__(256)
colstats_kernel(const float* __restrict__ S,
                float* __restrict__ cmax, float* __restrict__ cinv)
{
    __shared__ float mxs[256], sms[256];
    int tid = threadIdx.x;
    int c = tid & 63, rg = tid >> 6;
    int nb = blockIdx.x & 255;   // N/64 = 256 blocks per batch
    int b  = blockIdx.x >> 8;
    int n0 = nb * 64;

    size_t base = (size_t)b * MM * NN + (size_t)(n0 + c);
    float mx = -3e38f, s = 0.f;
    for (int m = rg; m < MM; m += 4) {
        float v = S[base + (size_t)m * NN];
        if (v > mx) { s = s * __expf(mx - v) + 1.f; mx = v; }
        else        { s += __expf(v - mx); }
    }
    mxs[tid] = mx; sms[tid] = s;
    __syncthreads();
    if (rg == 0) {
        #pragma unroll
        for (int k = 1; k < 4; ++k) {
            float m2 = mxs[k * 64 + c], s2 = sms[k * 64 + c];
            float Mx = fmaxf(mx, m2);
            s = s * __expf(mx - Mx) + s2 * __expf(m2 - Mx);
            mx = Mx;
        }
        cmax[b * NN + n0 + c] = mx;
        cinv[b * NN + n0 + c] = 1.f / s;
    }
}

// ---------------------------------------------------------------------------
// out[b,m,d] = sum_n softmax_w[b,m,n] * v[b,n,d] + v_features[b,m,d]
// 64(m) x 128(d) tile per block; exp applied on load of the S tile.
// smem: ws [64][65] + vs [64][132] = 50432 B (dynamic).
// ---------------------------------------------------------------------------
extern "C" __global__ void __launch_bounds__(256)
out_kernel(const float* __restrict__ S, const float* __restrict__ vv,
           const float* __restrict__ vfeat,
           const float* __restrict__ cmax, const float* __restrict__ cinv,
           float* __restrict__ out)
{
    extern __shared__ float smem[];
    float* ws = smem;            // [64][65]
    float* vs = smem + 64 * 65;  // [64][132]
    int tid = threadIdx.x, tx = tid & 15, ty = tid >> 4;
    int m0 = blockIdx.x * 64, b = blockIdx.y;

    float acc[4][8];
    #pragma unroll
    for (int i = 0; i < 4; ++i)
        #pragma unroll
        for (int j = 0; j < 8; ++j) acc[i][j] = 0.f;

    #pragma unroll 1
    for (int nc = 0; nc < NN / 64; ++nc) {
        int n0 = nc * 64;
        __syncthreads();
        for (int idx = tid; idx < 64 * 64; idx += 256) {
            int r = idx >> 6, cc = idx & 63;
            int gn = b * NN + n0 + cc;
            float sv = S[((size_t)(b * MM + m0 + r)) * NN + n0 + cc];
            ws[r * 65 + cc] = __expf(sv - __ldg(&cmax[gn])) * __ldg(&cinv[gn]);
        }
        for (int idx = tid; idx < 64 * 128; idx += 256) {
            int r = idx >> 7, d = idx & 127;
            vs[r * 132 + d] = vv[(size_t)(b * NN + n0 + r) * 128 + d];
        }
        __syncthreads();
        #pragma unroll 4
        for (int nn = 0; nn < 64; ++nn) {
            float a[4];
            #pragma unroll
            for (int i = 0; i < 4; ++i)
                a[i] = ws[(ty + 16 * i) * 65 + nn];
            float4 v0 = *(float4*)&vs[nn * 132 + tx * 8];
            float4 v1 = *(float4*)&vs[nn * 132 + tx * 8 + 4];
            #pragma unroll
            for (int i = 0; i < 4; ++i) {
                acc[i][0] += a[i] * v0.x; acc[i][1] += a[i] * v0.y;
                acc[i][2] += a[i] * v0.z; acc[i][3] += a[i] * v0.w;
                acc[i][4] += a[i] * v1.x; acc[i][5] += a[i] * v1.y;
                acc[i][6] += a[i] * v1.z; acc[i][7] += a[i] * v1.w;
            }
        }
    }

    #pragma unroll
    for (int i = 0; i < 4; ++i) {
        size_t o = (size_t)(b * MM + m0 + ty + 16 * i) * 128 + tx * 8;
        float4 f0 = *(float4*)&vfeat[o];
        float4 f1 = *(float4*)&vfeat[o + 4];
        f0.x += acc[i][0]; f0.y += acc[i][1]; f0.z += acc[i][2]; f0.w += acc[i][3];
        f1.x += acc[i][4]; f1.y += acc[i][5]; f1.z += acc[i][6]; f1.w += acc[i][7];
        *(float4*)&out[o]     = f0;
        *(float4*)&out[o + 4] = f1;
    }
}

// ---------------------------------------------------------------------------
extern "C" void kernel_launch(void* const* d_in, const int* in_sizes, int n_in,
                              void* d_out, int out_size)
{
    const float* p_xyz  = (const float*)d_in[0];
    const float* v_xyz  = (const float*)d_in[1];
    const float* p_feat = (const float*)d_in[2];
    const float* v_feat = (const float*)d_in[3];
    const float* aW1 = (const float*)d_in[4];
    const float* ab1 = (const float*)d_in[5];
    const float* aW2 = (const float*)d_in[6];
    const float* ab2 = (const float*)d_in[7];
    const float* bW1 = (const float*)d_in[8];
    const float* bb1 = (const float*)d_in[9];
    const float* bW2 = (const float*)d_in[10];
    const float* bb2 = (const float*)d_in[11];
    const float* oW1 = (const float*)d_in[12];
    const float* ob1 = (const float*)d_in[13];
    const float* oW2 = (const float*)d_in[14];
    const float* ob2 = (const float*)d_in[15];
    const float* dW1 = (const float*)d_in[16];
    const float* db1 = (const float*)d_in[17];
    const float* dW2 = (const float*)d_in[18];
    const float* db2 = (const float*)d_in[19];
    float* out = (float*)d_out;

    void *scores_p, *kpv_p, *v_p, *q_p, *cmax_p, *cinv_p;
    cudaGetSymbolAddress(&scores_p, g_scores);
    cudaGetSymbolAddress(&kpv_p,    g_kpv);
    cudaGetSymbolAddress(&v_p,      g_v);
    cudaGetSymbolAddress(&q_p,      g_q);
    cudaGetSymbolAddress(&cmax_p,   g_cmax);
    cudaGetSymbolAddress(&cinv_p,   g_cinv);

    cudaFuncSetAttribute(mlp128_kernel,
                         cudaFuncAttributeMaxDynamicSharedMemorySize, 49664);
    cudaFuncSetAttribute(delta_mlp_kernel,
                         cudaFuncAttributeMaxDynamicSharedMemorySize, 52224);
    cudaFuncSetAttribute(out_kernel,
                         cudaFuncAttributeMaxDynamicSharedMemorySize, 50432);

    // kpv = delta_mlp(|p - v|)
    delta_mlp_kernel<<<512, 256, 52224>>>(p_xyz, v_xyz, dW1, db1, dW2, db2,
                                          (float*)kpv_p);
    // kpv += beta_mlp(p_features)
    mlp128_kernel<<<512, 256, 49664>>>(p_feat, bW1, bb1, bW2, bb2,
                                       (float*)kpv_p, 1);
    // v = omega_mlp(p_features)
    mlp128_kernel<<<512, 256, 49664>>>(p_feat, oW1, ob1, oW2, ob2,
                                       (float*)v_p, 0);
    // q = alpha_mlp(v_features)
    mlp128_kernel<<<128, 256, 49664>>>(v_feat, aW1, ab1, aW2, ab2,
                                       (float*)q_p, 0);
    // S = scale * q @ kpv^T
    scores_kernel<<<dim3(128, 32, 2), 256>>>((const float*)q_p,
                                             (const float*)kpv_p,
                                             (float*)scores_p);
    // column softmax stats (over m)
    colstats_kernel<<<512, 256>>>((const float*)scores_p,
                                  (float*)cmax_p, (float*)cinv_p);
    // out = softmax(S) @ v + v_features
    out_kernel<<<dim3(64, 2), 256, 50432>>>((const float*)scores_p,
                                            (const float*)v_p, v_feat,
                                            (const float*)cmax_p,
                                            (const float*)cinv_p, out);
}

// round 4
// speedup vs baseline: 3.6880x; 3.6880x over previous
#include <cuda_runtime.h>
#include <cuda_bf16.h>
#include <cstdint>
#include <math.h>

#define BB 2
#define NN 16384
#define MM 4096
#define DD 128
#define SCALE 0.08838834764831845f   // 1/sqrt(128)
#define SEGS 8

// single consistent dynamic-smem declaration for ALL kernels
extern __shared__ __align__(1024) char hx_smem[];

// ---------------- scratch (device globals: no allocations allowed) ----------
__device__ __nv_bfloat16 g_S[(size_t)BB * MM * NN];     // 256 MB bf16 scores
__device__ float         g_kpvf[BB * NN * DD];          // delta MLP fp32
__device__ __nv_bfloat16 g_kpvb[BB * NN * DD];          // (k + pv) bf16
__device__ __nv_bfloat16 g_vT[BB * DD * NN];            // v transposed bf16
__device__ __nv_bfloat16 g_qb[BB * MM * DD];            // q bf16
__device__ float         g_cmax[BB * NN];
__device__ float         g_cinv[BB * NN];
__device__ float         g_part[SEGS * BB * MM * DD];   // split-K partials

// ====================== warp-MMA helpers (sm_80 baseline) ===================
__device__ __forceinline__ uint32_t smem_to_u32(const void* p) {
    uint32_t a;
    asm("{ .reg .u64 t; cvta.to.shared.u64 t, %1; cvt.u32.u64 %0, t; }"
        : "=r"(a) : "l"(p));
    return a;
}
__device__ __forceinline__ void ldsm_x4(uint32_t& r0, uint32_t& r1,
                                        uint32_t& r2, uint32_t& r3,
                                        uint32_t addr) {
    asm volatile("ldmatrix.sync.aligned.m8n8.x4.shared.b16 {%0,%1,%2,%3}, [%4];"
                 : "=r"(r0), "=r"(r1), "=r"(r2), "=r"(r3) : "r"(addr));
}
__device__ __forceinline__ void mma16816(float& c0, float& c1, float& c2, float& c3,
                                         uint32_t a0, uint32_t a1, uint32_t a2, uint32_t a3,
                                         uint32_t b0, uint32_t b1) {
    asm volatile("mma.sync.aligned.m16n8k16.row.col.f32.bf16.bf16.f32 "
                 "{%0,%1,%2,%3}, {%4,%5,%6,%7}, {%8,%9}, {%0,%1,%2,%3};"
                 : "+f"(c0), "+f"(c1), "+f"(c2), "+f"(c3)
                 : "r"(a0), "r"(a1), "r"(a2), "r"(a3), "r"(b0), "r"(b1));
}

// smem tile geometry: 128 rows x 128 bf16 data, row stride 136 bf16 (272 B)
#define RSTRIDE 136
#define TILE_BYTES (128 * RSTRIDE * 2)    // 34816

// copy a 128x128 bf16 row-major global tile into padded smem tile
__device__ __forceinline__ void load_tile(__nv_bfloat16* dst,
                                          const __nv_bfloat16* src,
                                          size_t src_stride, int tid) {
    const uint4* s = (const uint4*)src;
    uint4* d = (uint4*)dst;
    size_t sstr = src_stride >> 3;   // uint4 per src row
    #pragma unroll
    for (int idx = tid; idx < 2048; idx += 256) {
        int r = idx >> 4, c = idx & 15;
        d[r * 17 + c] = s[(size_t)r * sstr + c];
    }
}

// ============================ fp32 MLP kernels ==============================
__device__ __forceinline__ void mlp_phase(const float* __restrict__ sT,
                                          float* wch,
                                          const float* __restrict__ W,
                                          float acc[4][8],
                                          int tx, int ty, int tid)
{
    #pragma unroll 1
    for (int kc = 0; kc < 4; ++kc) {
        for (int idx = tid; idx < 32 * 128; idx += 256)
            wch[idx] = W[kc * 32 * 128 + idx];
        __syncthreads();
        #pragma unroll
        for (int dd = 0; dd < 32; ++dd) {
            float a[4];
            #pragma unroll
            for (int i = 0; i < 4; ++i)
                a[i] = sT[(kc * 32 + dd) * 65 + ty + 16 * i];
            float4 w0 = *(const float4*)&wch[dd * 128 + tx * 8];
            float4 w1 = *(const float4*)&wch[dd * 128 + tx * 8 + 4];
            #pragma unroll
            for (int i = 0; i < 4; ++i) {
                acc[i][0] += a[i] * w0.x; acc[i][1] += a[i] * w0.y;
                acc[i][2] += a[i] * w0.z; acc[i][3] += a[i] * w0.w;
                acc[i][4] += a[i] * w1.x; acc[i][5] += a[i] * w1.y;
                acc[i][6] += a[i] * w1.z; acc[i][7] += a[i] * w1.w;
            }
        }
        __syncthreads();
    }
}

// mode 0: write bf16 row-major.  mode 1: add fp32 addsrc, write bf16 row-major.
// mode 2: write bf16 transposed [b][d][n]  (for vT).
extern "C" __global__ void __launch_bounds__(256)
mlp128_kernel(const float* __restrict__ x,
              const float* __restrict__ W1, const float* __restrict__ b1,
              const float* __restrict__ W2, const float* __restrict__ b2,
              __nv_bfloat16* __restrict__ bfout,
              const float* __restrict__ addsrc, int mode)
{
    float* smem = (float*)hx_smem;
    float* sT  = smem;             // [128][65]
    float* wch = smem + 128 * 65;  // [32][128]
    int tid = threadIdx.x, tx = tid & 15, ty = tid >> 4;
    int row0 = blockIdx.x * 64;

    for (int idx = tid; idx < 64 * 128; idx += 256) {
        int r = idx >> 7, d = idx & 127;
        sT[d * 65 + r] = x[(size_t)(row0 + r) * 128 + d];
    }
    __syncthreads();

    float acc[4][8];
    #pragma unroll
    for (int i = 0; i < 4; ++i)
        #pragma unroll
        for (int j = 0; j < 8; ++j) acc[i][j] = 0.f;

    mlp_phase(sT, wch, W1, acc, tx, ty, tid);

    float bb[8];
    #pragma unroll
    for (int j = 0; j < 8; ++j) bb[j] = b1[tx * 8 + j];
    #pragma unroll
    for (int i = 0; i < 4; ++i)
        #pragma unroll
        for (int j = 0; j < 8; ++j) {
            float h = acc[i][j] + bb[j];
            sT[(tx * 8 + j) * 65 + ty + 16 * i] = h > 0.f ? h : 0.f;
            acc[i][j] = 0.f;
        }
    __syncthreads();

    mlp_phase(sT, wch, W2, acc, tx, ty, tid);

    #pragma unroll
    for (int j = 0; j < 8; ++j) bb[j] = b2[tx * 8 + j];

    if (mode == 2) {
        #pragma unroll
        for (int i = 0; i < 4; ++i)
            #pragma unroll
            for (int j = 0; j < 8; ++j)
                sT[(tx * 8 + j) * 65 + ty + 16 * i] = acc[i][j] + bb[j];
        __syncthreads();
        int b = row0 >> 14, nb = row0 & (NN - 1);
        for (int idx = tid; idx < 64 * 128; idx += 256) {
            int d = idx >> 6, r = idx & 63;
            bfout[((size_t)(b * DD + d)) * NN + nb + r] = __float2bfloat16(sT[d * 65 + r]);
        }
    } else {
        #pragma unroll
        for (int i = 0; i < 4; ++i) {
            size_t o = (size_t)(row0 + ty + 16 * i) * 128 + tx * 8;
            float v[8];
            #pragma unroll
            for (int j = 0; j < 8; ++j) v[j] = acc[i][j] + bb[j];
            if (mode == 1) {
                float4 a0 = *(const float4*)&addsrc[o];
                float4 a1 = *(const float4*)&addsrc[o + 4];
                v[0] += a0.x; v[1] += a0.y; v[2] += a0.z; v[3] += a0.w;
                v[4] += a1.x; v[5] += a1.y; v[6] += a1.z; v[7] += a1.w;
            }
            uint32_t pk[4];
            #pragma unroll
            for (int j = 0; j < 4; ++j) {
                __nv_bfloat162 p = __float22bfloat162_rn(make_float2(v[2*j], v[2*j+1]));
                pk[j] = *(uint32_t*)&p;
            }
            *(uint4*)(bfout + o) = *(uint4*)pk;
        }
    }
}

extern "C" __global__ void __launch_bounds__(256)
delta_mlp_kernel(const float* __restrict__ pxyz, const float* __restrict__ vxyz,
                 const float* __restrict__ W1, const float* __restrict__ b1,
                 const float* __restrict__ W2, const float* __restrict__ b2,
                 float* __restrict__ out)
{
    float* smem = (float*)hx_smem;
    float* sT  = smem;                 // [128][65]
    float* wch = smem + 128 * 65;      // [32][128]
    float* ds  = wch + 32 * 128;       // [64][4]
    float* w1s = ds + 64 * 4;          // [3][128]
    int tid = threadIdx.x, tx = tid & 15, ty = tid >> 4;
    int row0 = blockIdx.x * 64;

    if (tid < 192) {
        int r = tid / 3, c = tid % 3;
        int gr = row0 + r;
        int b = gr >> 14;
        ds[r * 4 + c] = fabsf(pxyz[(size_t)gr * 3 + c] - vxyz[b * 3 + c]);
    }
    for (int idx = tid; idx < 384; idx += 256) w1s[idx] = W1[idx];
    __syncthreads();

    for (int idx = tid; idx < 64 * 128; idx += 256) {
        int r = idx & 63, j = idx >> 6;
        float h = ds[r * 4] * w1s[j] + ds[r * 4 + 1] * w1s[128 + j] +
                  ds[r * 4 + 2] * w1s[256 + j] + b1[j];
        sT[j * 65 + r] = h > 0.f ? h : 0.f;
    }
    __syncthreads();

    float acc[4][8];
    #pragma unroll
    for (int i = 0; i < 4; ++i)
        #pragma unroll
        for (int j = 0; j < 8; ++j) acc[i][j] = 0.f;

    mlp_phase(sT, wch, W2, acc, tx, ty, tid);

    float bb[8];
    #pragma unroll
    for (int j = 0; j < 8; ++j) bb[j] = b2[tx * 8 + j];
    #pragma unroll
    for (int i = 0; i < 4; ++i) {
        size_t o = (size_t)(row0 + ty + 16 * i) * 128 + tx * 8;
        float4 v0 = make_float4(acc[i][0] + bb[0], acc[i][1] + bb[1],
                                acc[i][2] + bb[2], acc[i][3] + bb[3]);
        float4 v1 = make_float4(acc[i][4] + bb[4], acc[i][5] + bb[5],
                                acc[i][6] + bb[6], acc[i][7] + bb[7]);
        *(float4*)&out[o]     = v0;
        *(float4*)&out[o + 4] = v1;
    }
}

// =================== scores: warp-level bf16 HMMA GEMM ======================
// CTA: 128 m x 128 n, K = 128. 8 warps (2 x 4), warp tile 64 x 32.
extern "C" __global__ void __launch_bounds__(256)
scores_hmma_kernel(const __nv_bfloat16* __restrict__ qbf,
                   const __nv_bfloat16* __restrict__ kbf,
                   __nv_bfloat16* __restrict__ S)
{
    __nv_bfloat16* qs = (__nv_bfloat16*)hx_smem;
    __nv_bfloat16* ks = (__nv_bfloat16*)(hx_smem + TILE_BYTES);
    int tid = threadIdx.x, lane = tid & 31, w = tid >> 5;
    int wm = w >> 2, wn = w & 3;
    int n0 = blockIdx.x * 128, m0 = blockIdx.y * 128, b = blockIdx.z;

    load_tile(qs, qbf + (size_t)(b * MM + m0) * 128, 128, tid);
    load_tile(ks, kbf + (size_t)(b * NN + n0) * 128, 128, tid);
    __syncthreads();

    uint32_t qsb = smem_to_u32(qs), ksb = smem_to_u32(ks);
    // ldmatrix base offsets (per lane)
    uint32_t a_base = qsb + (uint32_t)(wm * 64 + (lane & 15)) * 272 + ((lane >> 4) << 4);
    uint32_t b_base = ksb + (uint32_t)(wn * 32 + (lane & 7) + ((lane >> 4) << 3)) * 272
                          + (((lane >> 3) & 1) << 4);

    float acc[4][4][4];
    #pragma unroll
    for (int i = 0; i < 4; ++i)
        #pragma unroll
        for (int j = 0; j < 4; ++j)
            #pragma unroll
            for (int t = 0; t < 4; ++t) acc[i][j][t] = 0.f;

    #pragma unroll
    for (int kk = 0; kk < 8; ++kk) {
        uint32_t a[4][4], bf[2][4];
        #pragma unroll
        for (int i = 0; i < 4; ++i)
            ldsm_x4(a[i][0], a[i][1], a[i][2], a[i][3],
                    a_base + i * 16 * 272 + kk * 32);
        #pragma unroll
        for (int j = 0; j < 2; ++j)
            ldsm_x4(bf[j][0], bf[j][1], bf[j][2], bf[j][3],
                    b_base + j * 16 * 272 + kk * 32);
        #pragma unroll
        for (int i = 0; i < 4; ++i)
            #pragma unroll
            for (int jt = 0; jt < 4; ++jt)
                mma16816(acc[i][jt][0], acc[i][jt][1], acc[i][jt][2], acc[i][jt][3],
                         a[i][0], a[i][1], a[i][2], a[i][3],
                         bf[jt >> 1][(jt & 1) * 2], bf[jt >> 1][(jt & 1) * 2 + 1]);
    }

    // epilogue: scale + bf16 pack, direct global stores
    size_t Sbase = (size_t)b * MM * NN;
    #pragma unroll
    for (int i = 0; i < 4; ++i) {
        int row = m0 + wm * 64 + i * 16 + (lane >> 2);
        #pragma unroll
        for (int jt = 0; jt < 4; ++jt) {
            int col = n0 + wn * 32 + jt * 8 + (lane & 3) * 2;
            __nv_bfloat162 p0 = __float22bfloat162_rn(
                make_float2(acc[i][jt][0] * SCALE, acc[i][jt][1] * SCALE));
            __nv_bfloat162 p1 = __float22bfloat162_rn(
                make_float2(acc[i][jt][2] * SCALE, acc[i][jt][3] * SCALE));
            *(uint32_t*)(S + Sbase + (size_t)row * NN + col)       = *(uint32_t*)&p0;
            *(uint32_t*)(S + Sbase + (size_t)(row + 8) * NN + col) = *(uint32_t*)&p1;
        }
    }
}

// ===================== column softmax stats (bf16 input) ====================
extern "C" __global__ void __launch_bounds__(256)
colstats_kernel(const __nv_bfloat16* __restrict__ S,
                float* __restrict__ cmax, float* __restrict__ cinv)
{
    __shared__ float mxs[2][256], sms[2][256];
    int tid = threadIdx.x, c = tid & 63, rg = tid >> 6;
    int n0 = blockIdx.x * 128, b = blockIdx.y;

    size_t base = (size_t)b * MM * NN + n0 + 2 * c;
    float mxa = -3e38f, sa = 0.f, mxb = -3e38f, sb2 = 0.f;
    for (int m = rg; m < MM; m += 4) {
        __nv_bfloat162 v2 = *(const __nv_bfloat162*)(S + base + (size_t)m * NN);
        float2 f = __bfloat1622float2(v2);
        if (f.x > mxa) { sa  = sa  * __expf(mxa - f.x) + 1.f; mxa = f.x; }
        else           { sa += __expf(f.x - mxa); }
        if (f.y > mxb) { sb2 = sb2 * __expf(mxb - f.y) + 1.f; mxb = f.y; }
        else           { sb2 += __expf(f.y - mxb); }
    }
    mxs[0][tid] = mxa; sms[0][tid] = sa;
    mxs[1][tid] = mxb; sms[1][tid] = sb2;
    __syncthreads();
    if (rg == 0) {
        #pragma unroll
        for (int k = 1; k < 4; ++k) {
            { float m2 = mxs[0][k*64+c], s2 = sms[0][k*64+c];
              float M = fmaxf(mxa, m2);
              sa = sa * __expf(mxa - M) + s2 * __expf(m2 - M); mxa = M; }
            { float m2 = mxs[1][k*64+c], s2 = sms[1][k*64+c];
              float M = fmaxf(mxb, m2);
              sb2 = sb2 * __expf(mxb - M) + s2 * __expf(m2 - M); mxb = M; }
        }
        int n = b * NN + n0 + 2 * c;
        cmax[n]     = mxa; cinv[n]     = 1.f / sa;
        cmax[n + 1] = mxb; cinv[n + 1] = 1.f / sb2;
    }
}

// ============== out: warp HMMA, split-K over n, fp32 partials ===============
// CTA: 128 m x 128 d; iterates 16384/SEGS/128 chunks of n within its segment.
extern "C" __global__ void __launch_bounds__(256)
out_hmma_kernel(const __nv_bfloat16* __restrict__ S,
                const __nv_bfloat16* __restrict__ vT,
                const float* __restrict__ cmax, const float* __restrict__ cinv,
                float* __restrict__ part)
{
    __nv_bfloat16* Ps = (__nv_bfloat16*)hx_smem;
    __nv_bfloat16* Vs = (__nv_bfloat16*)(hx_smem + TILE_BYTES);
    float* ci = (float*)(hx_smem + 2 * TILE_BYTES);   // 128 x (cmax, cinv)
    int tid = threadIdx.x, lane = tid & 31, w = tid >> 5;
    int wm = w >> 2, wn = w & 3;
    int m0 = blockIdx.x * 128, seg = blockIdx.y, b = blockIdx.z;
    int nbase = seg * (NN / SEGS);

    uint32_t psb = smem_to_u32(Ps), vsb = smem_to_u32(Vs);
    uint32_t a_base = psb + (uint32_t)(wm * 64 + (lane & 15)) * 272 + ((lane >> 4) << 4);
    uint32_t b_base = vsb + (uint32_t)(wn * 32 + (lane & 7) + ((lane >> 4) << 3)) * 272
                          + (((lane >> 3) & 1) << 4);

    const __nv_bfloat16* Sb = S  + ((size_t)b * MM + m0) * NN;
    const __nv_bfloat16* Vb = vT + (size_t)b * DD * NN;

    float acc[4][4][4];
    #pragma unroll
    for (int i = 0; i < 4; ++i)
        #pragma unroll
        for (int j = 0; j < 4; ++j)
            #pragma unroll
            for (int t = 0; t < 4; ++t) acc[i][j][t] = 0.f;

    #pragma unroll 1
    for (int ch = 0; ch < NN / SEGS / 128; ++ch) {
        int n0 = nbase + ch * 128;
        // stage (cmax, cinv) for these 128 columns
        if (tid < 128) {
            ci[2 * tid]     = cmax[b * NN + n0 + tid];
            ci[2 * tid + 1] = cinv[b * NN + n0 + tid];
        }
        __syncthreads();

        // P tile: exp(S - cmax) * cinv  -> bf16 in padded smem
        #pragma unroll
        for (int idx = tid; idx < 2048; idx += 256) {
            int r = idx >> 4, c = idx & 15;
            uint4 sv = *(const uint4*)(Sb + (size_t)r * NN + n0 + c * 8);
            __nv_bfloat162* sp = (__nv_bfloat162*)&sv;
            uint32_t pk[4];
            #pragma unroll
            for (int j = 0; j < 4; ++j) {
                float2 ff = __bfloat1622float2(sp[j]);
                float4 cc = *(float4*)&ci[2 * (c * 8 + 2 * j)];  // mx0,inv0,mx1,inv1
                float e0 = __expf(ff.x - cc.x) * cc.y;
                float e1 = __expf(ff.y - cc.z) * cc.w;
                __nv_bfloat162 p = __float22bfloat162_rn(make_float2(e0, e1));
                pk[j] = *(uint32_t*)&p;
            }
            ((uint4*)Ps)[r * 17 + c] = *(uint4*)pk;
        }
        // V tile (vT rows = d, cols = n)
        load_tile(Vs, Vb + n0, NN, tid);
        __syncthreads();

        #pragma unroll
        for (int kk = 0; kk < 8; ++kk) {
            uint32_t a[4][4], bf[2][4];
            #pragma unroll
            for (int i = 0; i < 4; ++i)
                ldsm_x4(a[i][0], a[i][1], a[i][2], a[i][3],
                        a_base + i * 16 * 272 + kk * 32);
            #pragma unroll
            for (int j = 0; j < 2; ++j)
                ldsm_x4(bf[j][0], bf[j][1], bf[j][2], bf[j][3],
                        b_base + j * 16 * 272 + kk * 32);
            #pragma unroll
            for (int i = 0; i < 4; ++i)
                #pragma unroll
                for (int jt = 0; jt < 4; ++jt)
                    mma16816(acc[i][jt][0], acc[i][jt][1], acc[i][jt][2], acc[i][jt][3],
                             a[i][0], a[i][1], a[i][2], a[i][3],
                             bf[jt >> 1][(jt & 1) * 2], bf[jt >> 1][(jt & 1) * 2 + 1]);
        }
        __syncthreads();
    }

    float* dst = part + ((size_t)(seg * BB + b) * MM) * DD;
    #pragma unroll
    for (int i = 0; i < 4; ++i) {
        int row = m0 + wm * 64 + i * 16 + (lane >> 2);
        #pragma unroll
        for (int jt = 0; jt < 4; ++jt) {
            int col = wn * 32 + jt * 8 + (lane & 3) * 2;
            *(float2*)(dst + (size_t)row * DD + col) =
                make_float2(acc[i][jt][0], acc[i][jt][1]);
            *(float2*)(dst + (size_t)(row + 8) * DD + col) =
                make_float2(acc[i][jt][2], acc[i][jt][3]);
        }
    }
}

// ===================== final reduce: out = vfeat + sum(partials) ============
extern "C" __global__ void __launch_bounds__(256)
reduce_kernel(const float* __restrict__ part, const float* __restrict__ vfeat,
              float* __restrict__ out)
{
    const size_t T = (size_t)BB * MM * DD;
    size_t i = ((size_t)blockIdx.x * 256 + threadIdx.x) * 4;
    float4 a = *(const float4*)(vfeat + i);
    #pragma unroll
    for (int s = 0; s < SEGS; ++s) {
        float4 p = *(const float4*)(part + s * T + i);
        a.x += p.x; a.y += p.y; a.z += p.z; a.w += p.w;
    }
    *(float4*)(out + i) = a;
}

// ---------------------------------------------------------------------------
extern "C" void kernel_launch(void* const* d_in, const int* in_sizes, int n_in,
                              void* d_out, int out_size)
{
    const float* p_xyz  = (const float*)d_in[0];
    const float* v_xyz  = (const float*)d_in[1];
    const float* p_feat = (const float*)d_in[2];
    const float* v_feat = (const float*)d_in[3];
    const float* aW1 = (const float*)d_in[4];
    const float* ab1 = (const float*)d_in[5];
    const float* aW2 = (const float*)d_in[6];
    const float* ab2 = (const float*)d_in[7];
    const float* bW1 = (const float*)d_in[8];
    const float* bb1 = (const float*)d_in[9];
    const float* bW2 = (const float*)d_in[10];
    const float* bb2 = (const float*)d_in[11];
    const float* oW1 = (const float*)d_in[12];
    const float* ob1 = (const float*)d_in[13];
    const float* oW2 = (const float*)d_in[14];
    const float* ob2 = (const float*)d_in[15];
    const float* dW1 = (const float*)d_in[16];
    const float* db1 = (const float*)d_in[17];
    const float* dW2 = (const float*)d_in[18];
    const float* db2 = (const float*)d_in[19];
    float* out = (float*)d_out;

    void *S_p, *kpvf_p, *kpvb_p, *vT_p, *qb_p, *cmax_p, *cinv_p, *part_p;
    cudaGetSymbolAddress(&S_p,    g_S);
    cudaGetSymbolAddress(&kpvf_p, g_kpvf);
    cudaGetSymbolAddress(&kpvb_p, g_kpvb);
    cudaGetSymbolAddress(&vT_p,   g_vT);
    cudaGetSymbolAddress(&qb_p,   g_qb);
    cudaGetSymbolAddress(&cmax_p, g_cmax);
    cudaGetSymbolAddress(&cinv_p, g_cinv);
    cudaGetSymbolAddress(&part_p, g_part);

    cudaFuncSetAttribute(mlp128_kernel,
                         cudaFuncAttributeMaxDynamicSharedMemorySize, 49664);
    cudaFuncSetAttribute(delta_mlp_kernel,
                         cudaFuncAttributeMaxDynamicSharedMemorySize, 52224);
    cudaFuncSetAttribute(scores_hmma_kernel,
                         cudaFuncAttributeMaxDynamicSharedMemorySize, 2 * TILE_BYTES);
    cudaFuncSetAttribute(out_hmma_kernel,
                         cudaFuncAttributeMaxDynamicSharedMemorySize, 2 * TILE_BYTES + 1024);

    // kpv(fp32) = delta_mlp(|p - v|)
    delta_mlp_kernel<<<512, 256, 52224>>>(p_xyz, v_xyz, dW1, db1, dW2, db2,
                                          (float*)kpvf_p);
    // kpv_bf16 = beta_mlp(p_features) + kpv(fp32)
    mlp128_kernel<<<512, 256, 49664>>>(p_feat, bW1, bb1, bW2, bb2,
                                       (__nv_bfloat16*)kpvb_p,
                                       (const float*)kpvf_p, 1);
    // vT_bf16 = omega_mlp(p_features)^T
    mlp128_kernel<<<512, 256, 49664>>>(p_feat, oW1, ob1, oW2, ob2,
                                       (__nv_bfloat16*)vT_p, nullptr, 2);
    // q_bf16 = alpha_mlp(v_features)
    mlp128_kernel<<<128, 256, 49664>>>(v_feat, aW1, ab1, aW2, ab2,
                                       (__nv_bfloat16*)qb_p, nullptr, 0);
    // S(bf16) = scale * q @ kpv^T   (HMMA)
    scores_hmma_kernel<<<dim3(128, 32, 2), 256, 2 * TILE_BYTES>>>(
        (const __nv_bfloat16*)qb_p, (const __nv_bfloat16*)kpvb_p,
        (__nv_bfloat16*)S_p);
    // column softmax stats over m
    colstats_kernel<<<dim3(128, 2), 256>>>((const __nv_bfloat16*)S_p,
                                           (float*)cmax_p, (float*)cinv_p);
    // partials = softmax(S) @ v   (HMMA, split-K = SEGS)
    out_hmma_kernel<<<dim3(32, SEGS, 2), 256, 2 * TILE_BYTES + 1024>>>(
        (const __nv_bfloat16*)S_p, (const __nv_bfloat16*)vT_p,
        (const float*)cmax_p, (const float*)cinv_p, (float*)part_p);
    // out = v_features + sum(partials)
    reduce_kernel<<<1024, 256>>>((const float*)part_p, v_feat, out);
}

// round 5
// speedup vs baseline: 4.3164x; 1.1704x over previous
#include <cuda_runtime.h>
#include <cuda_bf16.h>
#include <cstdint>
#include <math.h>

#define BB 2
#define NN 16384
#define MM 4096
#define DD 128
#define SCALE 0.08838834764831845f   // 1/sqrt(128)
#define SEGS 8

// single consistent dynamic-smem declaration for ALL kernels
extern __shared__ __align__(1024) char hx_smem[];

// ---------------- scratch (device globals: no allocations allowed) ----------
__device__ __nv_bfloat16 g_S[(size_t)BB * MM * NN];     // 256 MB bf16 scores
__device__ __nv_bfloat16 g_kpvb[BB * NN * DD];          // (k + pv) bf16
__device__ __nv_bfloat16 g_vT[BB * DD * NN];            // v transposed bf16
__device__ __nv_bfloat16 g_qb[BB * MM * DD];            // q bf16
__device__ float         g_cmax[BB * NN];
__device__ float         g_cinv[BB * NN];
__device__ float         g_part[SEGS * BB * MM * DD];   // split-K partials

// ====================== warp-MMA helpers (sm_80 baseline) ===================
__device__ __forceinline__ uint32_t smem_to_u32(const void* p) {
    uint32_t a;
    asm("{ .reg .u64 t; cvta.to.shared.u64 t, %1; cvt.u32.u64 %0, t; }"
        : "=r"(a) : "l"(p));
    return a;
}
__device__ __forceinline__ void ldsm_x4(uint32_t& r0, uint32_t& r1,
                                        uint32_t& r2, uint32_t& r3,
                                        uint32_t addr) {
    asm volatile("ldmatrix.sync.aligned.m8n8.x4.shared.b16 {%0,%1,%2,%3}, [%4];"
                 : "=r"(r0), "=r"(r1), "=r"(r2), "=r"(r3) : "r"(addr));
}
__device__ __forceinline__ void mma16816(float& c0, float& c1, float& c2, float& c3,
                                         uint32_t a0, uint32_t a1, uint32_t a2, uint32_t a3,
                                         uint32_t b0, uint32_t b1) {
    asm volatile("mma.sync.aligned.m16n8k16.row.col.f32.bf16.bf16.f32 "
                 "{%0,%1,%2,%3}, {%4,%5,%6,%7}, {%8,%9}, {%0,%1,%2,%3};"
                 : "+f"(c0), "+f"(c1), "+f"(c2), "+f"(c3)
                 : "r"(a0), "r"(a1), "r"(a2), "r"(a3), "r"(b0), "r"(b1));
}

// smem tile geometry: 128 rows x 128 bf16 data, row stride 136 bf16 (272 B)
#define RSTRIDE 136
#define TILE_BYTES (128 * RSTRIDE * 2)    // 34816

// per-lane ldmatrix base addresses (same mapping validated in scores kernel)
__device__ __forceinline__ uint32_t abase(uint32_t smem, int wm, int lane) {
    return smem + (uint32_t)(wm * 64 + (lane & 15)) * 272 + ((lane >> 4) << 4);
}
__device__ __forceinline__ uint32_t bbase(uint32_t smem, int wn, int lane) {
    return smem + (uint32_t)(wn * 32 + (lane & 7) + ((lane >> 4) << 3)) * 272
                + (((lane >> 3) & 1) << 4);
}

// one full 128x128x128 HMMA pass, accumulating into acc
__device__ __forceinline__ void hmma_pass(uint32_t a_base, uint32_t b_base,
                                          float acc[4][4][4]) {
    #pragma unroll
    for (int kk = 0; kk < 8; ++kk) {
        uint32_t a[4][4], bf[2][4];
        #pragma unroll
        for (int i = 0; i < 4; ++i)
            ldsm_x4(a[i][0], a[i][1], a[i][2], a[i][3],
                    a_base + i * 16 * 272 + kk * 32);
        #pragma unroll
        for (int j = 0; j < 2; ++j)
            ldsm_x4(bf[j][0], bf[j][1], bf[j][2], bf[j][3],
                    b_base + j * 16 * 272 + kk * 32);
        #pragma unroll
        for (int i = 0; i < 4; ++i)
            #pragma unroll
            for (int jt = 0; jt < 4; ++jt)
                mma16816(acc[i][jt][0], acc[i][jt][1], acc[i][jt][2], acc[i][jt][3],
                         a[i][0], a[i][1], a[i][2], a[i][3],
                         bf[jt >> 1][(jt & 1) * 2], bf[jt >> 1][(jt & 1) * 2 + 1]);
    }
}
#define ZERO_ACC(acc) {                                                  \
    _Pragma("unroll") for (int i = 0; i < 4; ++i)                        \
    _Pragma("unroll") for (int j = 0; j < 4; ++j)                        \
    _Pragma("unroll") for (int t = 0; t < 4; ++t) acc[i][j][t] = 0.f; }

// W[k][n] fp32 row-major -> ws[n][k] bf16 (B operand, transposed)
__device__ __forceinline__ void load_weightT(__nv_bfloat16* ws,
                                             const float* __restrict__ W,
                                             int tid) {
    for (int idx = tid; idx < 4096; idx += 256) {
        int k = idx >> 5, n4 = (idx & 31) * 4;
        float4 w = *(const float4*)&W[k * 128 + n4];
        ws[(n4 + 0) * RSTRIDE + k] = __float2bfloat16(w.x);
        ws[(n4 + 1) * RSTRIDE + k] = __float2bfloat16(w.y);
        ws[(n4 + 2) * RSTRIDE + k] = __float2bfloat16(w.z);
        ws[(n4 + 3) * RSTRIDE + k] = __float2bfloat16(w.w);
    }
}

// fp32 [rows][128] global -> bf16 padded smem tile
__device__ __forceinline__ void load_x_bf16(__nv_bfloat16* xs,
                                            const float* __restrict__ x,
                                            int tid) {
    for (int idx = tid; idx < 4096; idx += 256) {
        int r = idx >> 5, c4 = (idx & 31) * 4;
        float4 v = *(const float4*)&x[(size_t)r * 128 + c4];
        __nv_bfloat162 p0 = __float22bfloat162_rn(make_float2(v.x, v.y));
        __nv_bfloat162 p1 = __float22bfloat162_rn(make_float2(v.z, v.w));
        *(__nv_bfloat162*)(xs + r * RSTRIDE + c4)     = p0;
        *(__nv_bfloat162*)(xs + r * RSTRIDE + c4 + 2) = p1;
    }
}

// acc + bias (opt relu) -> bf16 hidden tile in smem
__device__ __forceinline__ void epi_hidden(__nv_bfloat16* hs, float acc[4][4][4],
                                           const float* __restrict__ bias,
                                           int wm, int wn, int lane, bool doRelu) {
    #pragma unroll
    for (int i = 0; i < 4; ++i) {
        int row = wm * 64 + i * 16 + (lane >> 2);
        #pragma unroll
        for (int jt = 0; jt < 4; ++jt) {
            int col = wn * 32 + jt * 8 + (lane & 3) * 2;
            float bx = __ldg(&bias[col]), by = __ldg(&bias[col + 1]);
            float v0 = acc[i][jt][0] + bx, v1 = acc[i][jt][1] + by;
            float v2 = acc[i][jt][2] + bx, v3 = acc[i][jt][3] + by;
            if (doRelu) {
                v0 = fmaxf(v0, 0.f); v1 = fmaxf(v1, 0.f);
                v2 = fmaxf(v2, 0.f); v3 = fmaxf(v3, 0.f);
            }
            *(__nv_bfloat162*)(hs + row * RSTRIDE + col) =
                __float22bfloat162_rn(make_float2(v0, v1));
            *(__nv_bfloat162*)(hs + (row + 8) * RSTRIDE + col) =
                __float22bfloat162_rn(make_float2(v2, v3));
        }
    }
}

// ================= points kernel: kpv (beta+delta) and vT (omega) ===========
// CTA handles 128 point rows. All GEMMs via HMMA.
extern "C" __global__ void __launch_bounds__(256)
points_mlp_hmma(const float* __restrict__ pfeat,
                const float* __restrict__ pxyz, const float* __restrict__ vxyz,
                const float* __restrict__ bW1, const float* __restrict__ bb1,
                const float* __restrict__ bW2, const float* __restrict__ bb2,
                const float* __restrict__ oW1, const float* __restrict__ ob1,
                const float* __restrict__ oW2, const float* __restrict__ ob2,
                const float* __restrict__ dW1, const float* __restrict__ db1,
                const float* __restrict__ dW2, const float* __restrict__ db2,
                __nv_bfloat16* __restrict__ kpvb, __nv_bfloat16* __restrict__ vT)
{
    __nv_bfloat16* xs = (__nv_bfloat16*)hx_smem;                 // input tile
    __nv_bfloat16* ha = (__nv_bfloat16*)(hx_smem + TILE_BYTES);  // hidden A
    __nv_bfloat16* hb = (__nv_bfloat16*)(hx_smem + 2 * TILE_BYTES); // hidden B
    __nv_bfloat16* ws = (__nv_bfloat16*)(hx_smem + 3 * TILE_BYTES); // weight tile
    float* ds  = (float*)(hx_smem + 4 * TILE_BYTES);             // [128][4] dist
    float* w1d = ds + 512;                                       // [3][128] dW1

    int tid = threadIdx.x, lane = tid & 31, w = tid >> 5;
    int wm = w >> 2, wn = w & 3;
    int row0 = blockIdx.x * 128;           // global point row (b*NN + n)
    int b = row0 >> 14, nb = row0 & (NN - 1);

    uint32_t xs_u = smem_to_u32(xs), ha_u = smem_to_u32(ha),
             hb_u = smem_to_u32(hb), ws_u = smem_to_u32(ws);
    uint32_t a_xs = abase(xs_u, wm, lane), a_ha = abase(ha_u, wm, lane),
             a_hb = abase(hb_u, wm, lane), b_ws = bbase(ws_u, wn, lane);

    // stage input, dist, delta W1
    load_x_bf16(xs, pfeat + (size_t)row0 * 128, tid);
    for (int idx = tid; idx < 384; idx += 256) {
        int r = idx / 3, c = idx % 3;
        ds[r * 4 + c] = fabsf(pxyz[(size_t)(row0 + r) * 3 + c] - vxyz[b * 3 + c]);
        w1d[idx < 128 ? idx : idx] = 0.f;  // placeholder; real load below
    }
    for (int idx = tid; idx < 384; idx += 256) w1d[idx] = dW1[idx];

    float acc[4][4][4];

    // ---- beta layer 1: ha = relu(xs @ bW1 + bb1)
    __syncthreads();
    load_weightT(ws, bW1, tid);
    __syncthreads();
    ZERO_ACC(acc);
    hmma_pass(a_xs, b_ws, acc);
    epi_hidden(ha, acc, bb1, wm, wn, lane, true);

    // ---- delta hidden: hb = relu(dist @ dW1 + db1)   (FFMA, din=3)
    for (int idx = tid; idx < 16384; idx += 256) {
        int r = idx >> 7, c = idx & 127;
        float h = ds[r * 4] * w1d[c] + ds[r * 4 + 1] * w1d[128 + c] +
                  ds[r * 4 + 2] * w1d[256 + c] + __ldg(&db1[c]);
        hb[r * RSTRIDE + c] = __float2bfloat16(fmaxf(h, 0.f));
    }

    // ---- kpv = ha @ bW2 + hb @ dW2 + (bb2 + db2)
    __syncthreads();
    load_weightT(ws, bW2, tid);
    __syncthreads();
    ZERO_ACC(acc);
    hmma_pass(a_ha, b_ws, acc);
    __syncthreads();
    load_weightT(ws, dW2, tid);
    __syncthreads();
    hmma_pass(a_hb, b_ws, acc);      // accumulate
    {
        __nv_bfloat16* dst = kpvb + (size_t)row0 * 128;
        #pragma unroll
        for (int i = 0; i < 4; ++i) {
            int row = wm * 64 + i * 16 + (lane >> 2);
            #pragma unroll
            for (int jt = 0; jt < 4; ++jt) {
                int col = wn * 32 + jt * 8 + (lane & 3) * 2;
                float bx = __ldg(&bb2[col]) + __ldg(&db2[col]);
                float by = __ldg(&bb2[col + 1]) + __ldg(&db2[col + 1]);
                __nv_bfloat162 p0 = __float22bfloat162_rn(
                    make_float2(acc[i][jt][0] + bx, acc[i][jt][1] + by));
                __nv_bfloat162 p1 = __float22bfloat162_rn(
                    make_float2(acc[i][jt][2] + bx, acc[i][jt][3] + by));
                *(uint32_t*)(dst + (size_t)row * 128 + col)       = *(uint32_t*)&p0;
                *(uint32_t*)(dst + (size_t)(row + 8) * 128 + col) = *(uint32_t*)&p1;
            }
        }
    }

    // ---- v = relu(xs @ oW1 + ob1) @ oW2 + ob2 -> transpose -> vT
    __syncthreads();
    load_weightT(ws, oW1, tid);
    __syncthreads();
    ZERO_ACC(acc);
    hmma_pass(a_xs, b_ws, acc);
    epi_hidden(ha, acc, ob1, wm, wn, lane, true);
    __syncthreads();
    load_weightT(ws, oW2, tid);
    __syncthreads();
    ZERO_ACC(acc);
    hmma_pass(a_ha, b_ws, acc);
    __syncthreads();                 // xs reads (omega L1) long done; reuse as xT
    #pragma unroll
    for (int i = 0; i < 4; ++i) {
        int row = wm * 64 + i * 16 + (lane >> 2);
        #pragma unroll
        for (int jt = 0; jt < 4; ++jt) {
            int col = wn * 32 + jt * 8 + (lane & 3) * 2;
            float bx = __ldg(&ob2[col]), by = __ldg(&ob2[col + 1]);
            xs[col * RSTRIDE + row]           = __float2bfloat16(acc[i][jt][0] + bx);
            xs[(col + 1) * RSTRIDE + row]     = __float2bfloat16(acc[i][jt][1] + by);
            xs[col * RSTRIDE + row + 8]       = __float2bfloat16(acc[i][jt][2] + bx);
            xs[(col + 1) * RSTRIDE + row + 8] = __float2bfloat16(acc[i][jt][3] + by);
        }
    }
    __syncthreads();
    for (int idx = tid; idx < 2048; idx += 256) {
        int d = idx >> 4, c8 = (idx & 15) * 8;
        uint4 v = *(uint4*)(xs + d * RSTRIDE + c8);
        *(uint4*)(vT + ((size_t)(b * DD + d)) * NN + nb + c8) = v;
    }
}

// ========================= q kernel: alpha MLP ==============================
extern "C" __global__ void __launch_bounds__(256)
q_mlp_hmma(const float* __restrict__ vfeat,
           const float* __restrict__ aW1, const float* __restrict__ ab1,
           const float* __restrict__ aW2, const float* __restrict__ ab2,
           __nv_bfloat16* __restrict__ qb)
{
    __nv_bfloat16* xs = (__nv_bfloat16*)hx_smem;
    __nv_bfloat16* ha = (__nv_bfloat16*)(hx_smem + TILE_BYTES);
    __nv_bfloat16* ws = (__nv_bfloat16*)(hx_smem + 2 * TILE_BYTES);
    int tid = threadIdx.x, lane = tid & 31, w = tid >> 5;
    int wm = w >> 2, wn = w & 3;
    int row0 = blockIdx.x * 128;

    uint32_t xs_u = smem_to_u32(xs), ha_u = smem_to_u32(ha), ws_u = smem_to_u32(ws);
    uint32_t a_xs = abase(xs_u, wm, lane), a_ha = abase(ha_u, wm, lane),
             b_ws = bbase(ws_u, wn, lane);

    load_x_bf16(xs, vfeat + (size_t)row0 * 128, tid);
    load_weightT(ws, aW1, tid);
    __syncthreads();

    float acc[4][4][4];
    ZERO_ACC(acc);
    hmma_pass(a_xs, b_ws, acc);
    epi_hidden(ha, acc, ab1, wm, wn, lane, true);
    __syncthreads();
    load_weightT(ws, aW2, tid);
    __syncthreads();
    ZERO_ACC(acc);
    hmma_pass(a_ha, b_ws, acc);

    __nv_bfloat16* dst = qb + (size_t)row0 * 128;
    #pragma unroll
    for (int i = 0; i < 4; ++i) {
        int row = wm * 64 + i * 16 + (lane >> 2);
        #pragma unroll
        for (int jt = 0; jt < 4; ++jt) {
            int col = wn * 32 + jt * 8 + (lane & 3) * 2;
            float bx = __ldg(&ab2[col]), by = __ldg(&ab2[col + 1]);
            __nv_bfloat162 p0 = __float22bfloat162_rn(
                make_float2(acc[i][jt][0] + bx, acc[i][jt][1] + by));
            __nv_bfloat162 p1 = __float22bfloat162_rn(
                make_float2(acc[i][jt][2] + bx, acc[i][jt][3] + by));
            *(uint32_t*)(dst + (size_t)row * 128 + col)       = *(uint32_t*)&p0;
            *(uint32_t*)(dst + (size_t)(row + 8) * 128 + col) = *(uint32_t*)&p1;
        }
    }
}

// copy a 128x128 bf16 row-major global tile into padded smem tile
__device__ __forceinline__ void load_tile(__nv_bfloat16* dst,
                                          const __nv_bfloat16* src,
                                          size_t src_stride, int tid) {
    const uint4* s = (const uint4*)src;
    uint4* d = (uint4*)dst;
    size_t sstr = src_stride >> 3;
    #pragma unroll
    for (int idx = tid; idx < 2048; idx += 256) {
        int r = idx >> 4, c = idx & 15;
        d[r * 17 + c] = s[(size_t)r * sstr + c];
    }
}

// =================== scores: warp-level bf16 HMMA GEMM ======================
extern "C" __global__ void __launch_bounds__(256)
scores_hmma_kernel(const __nv_bfloat16* __restrict__ qbf,
                   const __nv_bfloat16* __restrict__ kbf,
                   __nv_bfloat16* __restrict__ S)
{
    __nv_bfloat16* qs = (__nv_bfloat16*)hx_smem;
    __nv_bfloat16* ks = (__nv_bfloat16*)(hx_smem + TILE_BYTES);
    int tid = threadIdx.x, lane = tid & 31, w = tid >> 5;
    int wm = w >> 2, wn = w & 3;
    int n0 = blockIdx.x * 128, m0 = blockIdx.y * 128, b = blockIdx.z;

    load_tile(qs, qbf + (size_t)(b * MM + m0) * 128, 128, tid);
    load_tile(ks, kbf + (size_t)(b * NN + n0) * 128, 128, tid);
    __syncthreads();

    uint32_t a_base = abase(smem_to_u32(qs), wm, lane);
    uint32_t b_base = bbase(smem_to_u32(ks), wn, lane);

    float acc[4][4][4];
    ZERO_ACC(acc);
    hmma_pass(a_base, b_base, acc);

    size_t Sbase = (size_t)b * MM * NN;
    #pragma unroll
    for (int i = 0; i < 4; ++i) {
        int row = m0 + wm * 64 + i * 16 + (lane >> 2);
        #pragma unroll
        for (int jt = 0; jt < 4; ++jt) {
            int col = n0 + wn * 32 + jt * 8 + (lane & 3) * 2;
            __nv_bfloat162 p0 = __float22bfloat162_rn(
                make_float2(acc[i][jt][0] * SCALE, acc[i][jt][1] * SCALE));
            __nv_bfloat162 p1 = __float22bfloat162_rn(
                make_float2(acc[i][jt][2] * SCALE, acc[i][jt][3] * SCALE));
            *(uint32_t*)(S + Sbase + (size_t)row * NN + col)       = *(uint32_t*)&p0;
            *(uint32_t*)(S + Sbase + (size_t)(row + 8) * NN + col) = *(uint32_t*)&p1;
        }
    }
}

// ===================== column softmax stats (bf16 input) ====================
extern "C" __global__ void __launch_bounds__(256)
colstats_kernel(const __nv_bfloat16* __restrict__ S,
                float* __restrict__ cmax, float* __restrict__ cinv)
{
    __shared__ float mxs[2][256], sms[2][256];
    int tid = threadIdx.x, c = tid & 63, rg = tid >> 6;
    int n0 = blockIdx.x * 128, b = blockIdx.y;

    size_t base = (size_t)b * MM * NN + n0 + 2 * c;
    float mxa = -3e38f, sa = 0.f, mxb = -3e38f, sb2 = 0.f;
    for (int m = rg; m < MM; m += 4) {
        __nv_bfloat162 v2 = *(const __nv_bfloat162*)(S + base + (size_t)m * NN);
        float2 f = __bfloat1622float2(v2);
        if (f.x > mxa) { sa  = sa  * __expf(mxa - f.x) + 1.f; mxa = f.x; }
        else           { sa += __expf(f.x - mxa); }
        if (f.y > mxb) { sb2 = sb2 * __expf(mxb - f.y) + 1.f; mxb = f.y; }
        else           { sb2 += __expf(f.y - mxb); }
    }
    mxs[0][tid] = mxa; sms[0][tid] = sa;
    mxs[1][tid] = mxb; sms[1][tid] = sb2;
    __syncthreads();
    if (rg == 0) {
        #pragma unroll
        for (int k = 1; k < 4; ++k) {
            { float m2 = mxs[0][k*64+c], s2 = sms[0][k*64+c];
              float M = fmaxf(mxa, m2);
              sa = sa * __expf(mxa - M) + s2 * __expf(m2 - M); mxa = M; }
            { float m2 = mxs[1][k*64+c], s2 = sms[1][k*64+c];
              float M = fmaxf(mxb, m2);
              sb2 = sb2 * __expf(mxb - M) + s2 * __expf(m2 - M); mxb = M; }
        }
        int n = b * NN + n0 + 2 * c;
        cmax[n]     = mxa; cinv[n]     = 1.f / sa;
        cmax[n + 1] = mxb; cinv[n + 1] = 1.f / sb2;
    }
}

// ============== out: warp HMMA, split-K over n, fp32 partials ===============
extern "C" __global__ void __launch_bounds__(256)
out_hmma_kernel(const __nv_bfloat16* __restrict__ S,
                const __nv_bfloat16* __restrict__ vT,
                const float* __restrict__ cmax, const float* __restrict__ cinv,
                float* __restrict__ part)
{
    __nv_bfloat16* Ps = (__nv_bfloat16*)hx_smem;
    __nv_bfloat16* Vs = (__nv_bfloat16*)(hx_smem + TILE_BYTES);
    float* ci = (float*)(hx_smem + 2 * TILE_BYTES);
    int tid = threadIdx.x, lane = tid & 31, w = tid >> 5;
    int wm = w >> 2, wn = w & 3;
    int m0 = blockIdx.x * 128, seg = blockIdx.y, b = blockIdx.z;
    int nbase = seg * (NN / SEGS);

    uint32_t a_base = abase(smem_to_u32(Ps), wm, lane);
    uint32_t b_base = bbase(smem_to_u32(Vs), wn, lane);

    const __nv_bfloat16* Sb = S  + ((size_t)b * MM + m0) * NN;
    const __nv_bfloat16* Vb = vT + (size_t)b * DD * NN;

    float acc[4][4][4];
    ZERO_ACC(acc);

    #pragma unroll 1
    for (int ch = 0; ch < NN / SEGS / 128; ++ch) {
        int n0 = nbase + ch * 128;
        if (tid < 128) {
            ci[2 * tid]     = cmax[b * NN + n0 + tid];
            ci[2 * tid + 1] = cinv[b * NN + n0 + tid];
        }
        __syncthreads();

        #pragma unroll
        for (int idx = tid; idx < 2048; idx += 256) {
            int r = idx >> 4, c = idx & 15;
            uint4 sv = *(const uint4*)(Sb + (size_t)r * NN + n0 + c * 8);
            __nv_bfloat162* sp = (__nv_bfloat162*)&sv;
            uint32_t pk[4];
            #pragma unroll
            for (int j = 0; j < 4; ++j) {
                float2 ff = __bfloat1622float2(sp[j]);
                float4 cc = *(float4*)&ci[2 * (c * 8 + 2 * j)];
                float e0 = __expf(ff.x - cc.x) * cc.y;
                float e1 = __expf(ff.y - cc.z) * cc.w;
                __nv_bfloat162 p = __float22bfloat162_rn(make_float2(e0, e1));
                pk[j] = *(uint32_t*)&p;
            }
            ((uint4*)Ps)[r * 17 + c] = *(uint4*)pk;
        }
        load_tile(Vs, Vb + n0, NN, tid);
        __syncthreads();

        hmma_pass(a_base, b_base, acc);
        __syncthreads();
    }

    float* dst = part + ((size_t)(seg * BB + b) * MM) * DD;
    #pragma unroll
    for (int i = 0; i < 4; ++i) {
        int row = m0 + wm * 64 + i * 16 + (lane >> 2);
        #pragma unroll
        for (int jt = 0; jt < 4; ++jt) {
            int col = wn * 32 + jt * 8 + (lane & 3) * 2;
            *(float2*)(dst + (size_t)row * DD + col) =
                make_float2(acc[i][jt][0], acc[i][jt][1]);
            *(float2*)(dst + (size_t)(row + 8) * DD + col) =
                make_float2(acc[i][jt][2], acc[i][jt][3]);
        }
    }
}

// ===================== final reduce: out = vfeat + sum(partials) ============
extern "C" __global__ void __launch_bounds__(256)
reduce_kernel(const float* __restrict__ part, const float* __restrict__ vfeat,
              float* __restrict__ out)
{
    const size_t T = (size_t)BB * MM * DD;
    size_t i = ((size_t)blockIdx.x * 256 + threadIdx.x) * 4;
    float4 a = *(const float4*)(vfeat + i);
    #pragma unroll
    for (int s = 0; s < SEGS; ++s) {
        float4 p = *(const float4*)(part + s * T + i);
        a.x += p.x; a.y += p.y; a.z += p.z; a.w += p.w;
    }
    *(float4*)(out + i) = a;
}

// ---------------------------------------------------------------------------
extern "C" void kernel_launch(void* const* d_in, const int* in_sizes, int n_in,
                              void* d_out, int out_size)
{
    const float* p_xyz  = (const float*)d_in[0];
    const float* v_xyz  = (const float*)d_in[1];
    const float* p_feat = (const float*)d_in[2];
    const float* v_feat = (const float*)d_in[3];
    const float* aW1 = (const float*)d_in[4];
    const float* ab1 = (const float*)d_in[5];
    const float* aW2 = (const float*)d_in[6];
    const float* ab2 = (const float*)d_in[7];
    const float* bW1 = (const float*)d_in[8];
    const float* bb1 = (const float*)d_in[9];
    const float* bW2 = (const float*)d_in[10];
    const float* bb2 = (const float*)d_in[11];
    const float* oW1 = (const float*)d_in[12];
    const float* ob1 = (const float*)d_in[13];
    const float* oW2 = (const float*)d_in[14];
    const float* ob2 = (const float*)d_in[15];
    const float* dW1 = (const float*)d_in[16];
    const float* db1 = (const float*)d_in[17];
    const float* dW2 = (const float*)d_in[18];
    const float* db2 = (const float*)d_in[19];
    float* out = (float*)d_out;

    void *S_p, *kpvb_p, *vT_p, *qb_p, *cmax_p, *cinv_p, *part_p;
    cudaGetSymbolAddress(&S_p,    g_S);
    cudaGetSymbolAddress(&kpvb_p, g_kpvb);
    cudaGetSymbolAddress(&vT_p,   g_vT);
    cudaGetSymbolAddress(&qb_p,   g_qb);
    cudaGetSymbolAddress(&cmax_p, g_cmax);
    cudaGetSymbolAddress(&cinv_p, g_cinv);
    cudaGetSymbolAddress(&part_p, g_part);

    const int PTS_SMEM = 4 * TILE_BYTES + 2048 + 1536;     // 142848
    cudaFuncSetAttribute(points_mlp_hmma,
                         cudaFuncAttributeMaxDynamicSharedMemorySize, PTS_SMEM);
    cudaFuncSetAttribute(q_mlp_hmma,
                         cudaFuncAttributeMaxDynamicSharedMemorySize, 3 * TILE_BYTES);
    cudaFuncSetAttribute(scores_hmma_kernel,
                         cudaFuncAttributeMaxDynamicSharedMemorySize, 2 * TILE_BYTES);
    cudaFuncSetAttribute(out_hmma_kernel,
                         cudaFuncAttributeMaxDynamicSharedMemorySize, 2 * TILE_BYTES + 1024);

    // kpv bf16 + vT bf16 from p_features / p_xyz (beta + delta + omega, HMMA)
    points_mlp_hmma<<<256, 256, PTS_SMEM>>>(
        p_feat, p_xyz, v_xyz,
        bW1, bb1, bW2, bb2, oW1, ob1, oW2, ob2, dW1, db1, dW2, db2,
        (__nv_bfloat16*)kpvb_p, (__nv_bfloat16*)vT_p);
    // q bf16 (alpha, HMMA)
    q_mlp_hmma<<<64, 256, 3 * TILE_BYTES>>>(
        v_feat, aW1, ab1, aW2, ab2, (__nv_bfloat16*)qb_p);
    // S(bf16) = scale * q @ kpv^T
    scores_hmma_kernel<<<dim3(128, 32, 2), 256, 2 * TILE_BYTES>>>(
        (const __nv_bfloat16*)qb_p, (const __nv_bfloat16*)kpvb_p,
        (__nv_bfloat16*)S_p);
    // column softmax stats over m
    colstats_kernel<<<dim3(128, 2), 256>>>((const __nv_bfloat16*)S_p,
                                           (float*)cmax_p, (float*)cinv_p);
    // partials = softmax(S) @ v   (HMMA, split-K = SEGS)
    out_hmma_kernel<<<dim3(32, SEGS, 2), 256, 2 * TILE_BYTES + 1024>>>(
        (const __nv_bfloat16*)S_p, (const __nv_bfloat16*)vT_p,
        (const float*)cmax_p, (const float*)cinv_p, (float*)part_p);
    // out = v_features + sum(partials)
    reduce_kernel<<<1024, 256>>>((const float*)part_p, v_feat, out);
}

// round 6
// speedup vs baseline: 9.3501x; 2.1662x over previous
#include <cuda_runtime.h>
#include <cuda_bf16.h>
#include <cstdint>
#include <math.h>

#define BB 2
#define NN 16384
#define MM 4096
#define DD 128
#define SCALE 0.08838834764831845f   // 1/sqrt(128)
#define SEGS 8
#define MTILES 32                     // MM / 128

// single consistent dynamic-smem declaration for ALL kernels
extern __shared__ __align__(1024) char hx_smem[];

// ---------------- scratch (device globals: no allocations allowed) ----------
__device__ __nv_bfloat16 g_S[(size_t)BB * MM * NN];     // 256 MB bf16 exp(scores)
__device__ __nv_bfloat16 g_kpvb[BB * NN * DD];          // (k + pv) bf16
__device__ __nv_bfloat16 g_vT[BB * DD * NN];            // v transposed bf16
__device__ __nv_bfloat16 g_qb[BB * MM * DD];            // q bf16
__device__ float         g_psum[MTILES * BB * NN];      // per-mtile col sums
__device__ float         g_cinv[BB * NN];
__device__ float         g_part[SEGS * BB * MM * DD];   // split-K partials

// ====================== warp-MMA helpers (sm_80 baseline) ===================
__device__ __forceinline__ uint32_t smem_to_u32(const void* p) {
    uint32_t a;
    asm("{ .reg .u64 t; cvta.to.shared.u64 t, %1; cvt.u32.u64 %0, t; }"
        : "=r"(a) : "l"(p));
    return a;
}
__device__ __forceinline__ void ldsm_x4(uint32_t& r0, uint32_t& r1,
                                        uint32_t& r2, uint32_t& r3,
                                        uint32_t addr) {
    asm volatile("ldmatrix.sync.aligned.m8n8.x4.shared.b16 {%0,%1,%2,%3}, [%4];"
                 : "=r"(r0), "=r"(r1), "=r"(r2), "=r"(r3) : "r"(addr));
}
__device__ __forceinline__ void mma16816(float& c0, float& c1, float& c2, float& c3,
                                         uint32_t a0, uint32_t a1, uint32_t a2, uint32_t a3,
                                         uint32_t b0, uint32_t b1) {
    asm volatile("mma.sync.aligned.m16n8k16.row.col.f32.bf16.bf16.f32 "
                 "{%0,%1,%2,%3}, {%4,%5,%6,%7}, {%8,%9}, {%0,%1,%2,%3};"
                 : "+f"(c0), "+f"(c1), "+f"(c2), "+f"(c3)
                 : "r"(a0), "r"(a1), "r"(a2), "r"(a3), "r"(b0), "r"(b1));
}

// smem tile geometry: 128 rows x 128 bf16 data, row stride 136 bf16 (272 B)
#define RSTRIDE 136
#define TILE_BYTES (128 * RSTRIDE * 2)    // 34816

__device__ __forceinline__ uint32_t abase(uint32_t smem, int wm, int lane) {
    return smem + (uint32_t)(wm * 64 + (lane & 15)) * 272 + ((lane >> 4) << 4);
}
__device__ __forceinline__ uint32_t bbase(uint32_t smem, int wn, int lane) {
    return smem + (uint32_t)(wn * 32 + (lane & 7) + ((lane >> 4) << 3)) * 272
                + (((lane >> 3) & 1) << 4);
}

__device__ __forceinline__ void hmma_pass(uint32_t a_base, uint32_t b_base,
                                          float acc[4][4][4]) {
    #pragma unroll
    for (int kk = 0; kk < 8; ++kk) {
        uint32_t a[4][4], bf[2][4];
        #pragma unroll
        for (int i = 0; i < 4; ++i)
            ldsm_x4(a[i][0], a[i][1], a[i][2], a[i][3],
                    a_base + i * 16 * 272 + kk * 32);
        #pragma unroll
        for (int j = 0; j < 2; ++j)
            ldsm_x4(bf[j][0], bf[j][1], bf[j][2], bf[j][3],
                    b_base + j * 16 * 272 + kk * 32);
        #pragma unroll
        for (int i = 0; i < 4; ++i)
            #pragma unroll
            for (int jt = 0; jt < 4; ++jt)
                mma16816(acc[i][jt][0], acc[i][jt][1], acc[i][jt][2], acc[i][jt][3],
                         a[i][0], a[i][1], a[i][2], a[i][3],
                         bf[jt >> 1][(jt & 1) * 2], bf[jt >> 1][(jt & 1) * 2 + 1]);
    }
}
#define ZERO_ACC(acc) {                                                  \
    _Pragma("unroll") for (int i = 0; i < 4; ++i)                        \
    _Pragma("unroll") for (int j = 0; j < 4; ++j)                        \
    _Pragma("unroll") for (int t = 0; t < 4; ++t) acc[i][j][t] = 0.f; }

// W[k][n] fp32 row-major -> ws[n][k] bf16 (B operand, transposed)
__device__ __forceinline__ void load_weightT(__nv_bfloat16* ws,
                                             const float* __restrict__ W,
                                             int tid) {
    for (int idx = tid; idx < 4096; idx += 256) {
        int k = idx >> 5, n4 = (idx & 31) * 4;
        float4 w = *(const float4*)&W[k * 128 + n4];
        ws[(n4 + 0) * RSTRIDE + k] = __float2bfloat16(w.x);
        ws[(n4 + 1) * RSTRIDE + k] = __float2bfloat16(w.y);
        ws[(n4 + 2) * RSTRIDE + k] = __float2bfloat16(w.z);
        ws[(n4 + 3) * RSTRIDE + k] = __float2bfloat16(w.w);
    }
}

__device__ __forceinline__ void load_x_bf16(__nv_bfloat16* xs,
                                            const float* __restrict__ x,
                                            int tid) {
    for (int idx = tid; idx < 4096; idx += 256) {
        int r = idx >> 5, c4 = (idx & 31) * 4;
        float4 v = *(const float4*)&x[(size_t)r * 128 + c4];
        __nv_bfloat162 p0 = __float22bfloat162_rn(make_float2(v.x, v.y));
        __nv_bfloat162 p1 = __float22bfloat162_rn(make_float2(v.z, v.w));
        *(__nv_bfloat162*)(xs + r * RSTRIDE + c4)     = p0;
        *(__nv_bfloat162*)(xs + r * RSTRIDE + c4 + 2) = p1;
    }
}

__device__ __forceinline__ void epi_hidden(__nv_bfloat16* hs, float acc[4][4][4],
                                           const float* __restrict__ bias,
                                           int wm, int wn, int lane, bool doRelu) {
    #pragma unroll
    for (int i = 0; i < 4; ++i) {
        int row = wm * 64 + i * 16 + (lane >> 2);
        #pragma unroll
        for (int jt = 0; jt < 4; ++jt) {
            int col = wn * 32 + jt * 8 + (lane & 3) * 2;
            float bx = __ldg(&bias[col]), by = __ldg(&bias[col + 1]);
            float v0 = acc[i][jt][0] + bx, v1 = acc[i][jt][1] + by;
            float v2 = acc[i][jt][2] + bx, v3 = acc[i][jt][3] + by;
            if (doRelu) {
                v0 = fmaxf(v0, 0.f); v1 = fmaxf(v1, 0.f);
                v2 = fmaxf(v2, 0.f); v3 = fmaxf(v3, 0.f);
            }
            *(__nv_bfloat162*)(hs + row * RSTRIDE + col) =
                __float22bfloat162_rn(make_float2(v0, v1));
            *(__nv_bfloat162*)(hs + (row + 8) * RSTRIDE + col) =
                __float22bfloat162_rn(make_float2(v2, v3));
        }
    }
}

// ================= points kernel: kpv (beta+delta) and vT (omega) ===========
extern "C" __global__ void __launch_bounds__(256)
points_mlp_hmma(const float* __restrict__ pfeat,
                const float* __restrict__ pxyz, const float* __restrict__ vxyz,
                const float* __restrict__ bW1, const float* __restrict__ bb1,
                const float* __restrict__ bW2, const float* __restrict__ bb2,
                const float* __restrict__ oW1, const float* __restrict__ ob1,
                const float* __restrict__ oW2, const float* __restrict__ ob2,
                const float* __restrict__ dW1, const float* __restrict__ db1,
                const float* __restrict__ dW2, const float* __restrict__ db2,
                __nv_bfloat16* __restrict__ kpvb, __nv_bfloat16* __restrict__ vT)
{
    __nv_bfloat16* xs = (__nv_bfloat16*)hx_smem;
    __nv_bfloat16* ha = (__nv_bfloat16*)(hx_smem + TILE_BYTES);
    __nv_bfloat16* hb = (__nv_bfloat16*)(hx_smem + 2 * TILE_BYTES);
    __nv_bfloat16* ws = (__nv_bfloat16*)(hx_smem + 3 * TILE_BYTES);
    float* ds  = (float*)(hx_smem + 4 * TILE_BYTES);
    float* w1d = ds + 512;

    int tid = threadIdx.x, lane = tid & 31, w = tid >> 5;
    int wm = w >> 2, wn = w & 3;
    int row0 = blockIdx.x * 128;
    int b = row0 >> 14, nb = row0 & (NN - 1);

    uint32_t a_xs = abase(smem_to_u32(xs), wm, lane),
             a_ha = abase(smem_to_u32(ha), wm, lane),
             a_hb = abase(smem_to_u32(hb), wm, lane),
             b_ws = bbase(smem_to_u32(ws), wn, lane);

    load_x_bf16(xs, pfeat + (size_t)row0 * 128, tid);
    for (int idx = tid; idx < 384; idx += 256) {
        int r = idx / 3, c = idx % 3;
        ds[r * 4 + c] = fabsf(pxyz[(size_t)(row0 + r) * 3 + c] - vxyz[b * 3 + c]);
    }
    for (int idx = tid; idx < 384; idx += 256) w1d[idx] = dW1[idx];

    float acc[4][4][4];

    __syncthreads();
    load_weightT(ws, bW1, tid);
    __syncthreads();
    ZERO_ACC(acc);
    hmma_pass(a_xs, b_ws, acc);
    epi_hidden(ha, acc, bb1, wm, wn, lane, true);

    for (int idx = tid; idx < 16384; idx += 256) {
        int r = idx >> 7, c = idx & 127;
        float h = ds[r * 4] * w1d[c] + ds[r * 4 + 1] * w1d[128 + c] +
                  ds[r * 4 + 2] * w1d[256 + c] + __ldg(&db1[c]);
        hb[r * RSTRIDE + c] = __float2bfloat16(fmaxf(h, 0.f));
    }

    __syncthreads();
    load_weightT(ws, bW2, tid);
    __syncthreads();
    ZERO_ACC(acc);
    hmma_pass(a_ha, b_ws, acc);
    __syncthreads();
    load_weightT(ws, dW2, tid);
    __syncthreads();
    hmma_pass(a_hb, b_ws, acc);
    {
        __nv_bfloat16* dst = kpvb + (size_t)row0 * 128;
        #pragma unroll
        for (int i = 0; i < 4; ++i) {
            int row = wm * 64 + i * 16 + (lane >> 2);
            #pragma unroll
            for (int jt = 0; jt < 4; ++jt) {
                int col = wn * 32 + jt * 8 + (lane & 3) * 2;
                float bx = __ldg(&bb2[col]) + __ldg(&db2[col]);
                float by = __ldg(&bb2[col + 1]) + __ldg(&db2[col + 1]);
                __nv_bfloat162 p0 = __float22bfloat162_rn(
                    make_float2(acc[i][jt][0] + bx, acc[i][jt][1] + by));
                __nv_bfloat162 p1 = __float22bfloat162_rn(
                    make_float2(acc[i][jt][2] + bx, acc[i][jt][3] + by));
                *(uint32_t*)(dst + (size_t)row * 128 + col)       = *(uint32_t*)&p0;
                *(uint32_t*)(dst + (size_t)(row + 8) * 128 + col) = *(uint32_t*)&p1;
            }
        }
    }

    __syncthreads();
    load_weightT(ws, oW1, tid);
    __syncthreads();
    ZERO_ACC(acc);
    hmma_pass(a_xs, b_ws, acc);
    epi_hidden(ha, acc, ob1, wm, wn, lane, true);
    __syncthreads();
    load_weightT(ws, oW2, tid);
    __syncthreads();
    ZERO_ACC(acc);
    hmma_pass(a_ha, b_ws, acc);
    __syncthreads();
    #pragma unroll
    for (int i = 0; i < 4; ++i) {
        int row = wm * 64 + i * 16 + (lane >> 2);
        #pragma unroll
        for (int jt = 0; jt < 4; ++jt) {
            int col = wn * 32 + jt * 8 + (lane & 3) * 2;
            float bx = __ldg(&ob2[col]), by = __ldg(&ob2[col + 1]);
            xs[col * RSTRIDE + row]           = __float2bfloat16(acc[i][jt][0] + bx);
            xs[(col + 1) * RSTRIDE + row]     = __float2bfloat16(acc[i][jt][1] + by);
            xs[col * RSTRIDE + row + 8]       = __float2bfloat16(acc[i][jt][2] + bx);
            xs[(col + 1) * RSTRIDE + row + 8] = __float2bfloat16(acc[i][jt][3] + by);
        }
    }
    __syncthreads();
    for (int idx = tid; idx < 2048; idx += 256) {
        int d = idx >> 4, c8 = (idx & 15) * 8;
        uint4 v = *(uint4*)(xs + d * RSTRIDE + c8);
        *(uint4*)(vT + ((size_t)(b * DD + d)) * NN + nb + c8) = v;
    }
}

// ========================= q kernel: alpha MLP ==============================
extern "C" __global__ void __launch_bounds__(256)
q_mlp_hmma(const float* __restrict__ vfeat,
           const float* __restrict__ aW1, const float* __restrict__ ab1,
           const float* __restrict__ aW2, const float* __restrict__ ab2,
           __nv_bfloat16* __restrict__ qb)
{
    __nv_bfloat16* xs = (__nv_bfloat16*)hx_smem;
    __nv_bfloat16* ha = (__nv_bfloat16*)(hx_smem + TILE_BYTES);
    __nv_bfloat16* ws = (__nv_bfloat16*)(hx_smem + 2 * TILE_BYTES);
    int tid = threadIdx.x, lane = tid & 31, w = tid >> 5;
    int wm = w >> 2, wn = w & 3;
    int row0 = blockIdx.x * 128;

    uint32_t a_xs = abase(smem_to_u32(xs), wm, lane),
             a_ha = abase(smem_to_u32(ha), wm, lane),
             b_ws = bbase(smem_to_u32(ws), wn, lane);

    load_x_bf16(xs, vfeat + (size_t)row0 * 128, tid);
    load_weightT(ws, aW1, tid);
    __syncthreads();

    float acc[4][4][4];
    ZERO_ACC(acc);
    hmma_pass(a_xs, b_ws, acc);
    epi_hidden(ha, acc, ab1, wm, wn, lane, true);
    __syncthreads();
    load_weightT(ws, aW2, tid);
    __syncthreads();
    ZERO_ACC(acc);
    hmma_pass(a_ha, b_ws, acc);

    __nv_bfloat16* dst = qb + (size_t)row0 * 128;
    #pragma unroll
    for (int i = 0; i < 4; ++i) {
        int row = wm * 64 + i * 16 + (lane >> 2);
        #pragma unroll
        for (int jt = 0; jt < 4; ++jt) {
            int col = wn * 32 + jt * 8 + (lane & 3) * 2;
            float bx = __ldg(&ab2[col]), by = __ldg(&ab2[col + 1]);
            __nv_bfloat162 p0 = __float22bfloat162_rn(
                make_float2(acc[i][jt][0] + bx, acc[i][jt][1] + by));
            __nv_bfloat162 p1 = __float22bfloat162_rn(
                make_float2(acc[i][jt][2] + bx, acc[i][jt][3] + by));
            *(uint32_t*)(dst + (size_t)row * 128 + col)       = *(uint32_t*)&p0;
            *(uint32_t*)(dst + (size_t)(row + 8) * 128 + col) = *(uint32_t*)&p1;
        }
    }
}

// copy a 128x128 bf16 row-major global tile into padded smem tile
__device__ __forceinline__ void load_tile(__nv_bfloat16* dst,
                                          const __nv_bfloat16* src,
                                          size_t src_stride, int tid) {
    const uint4* s = (const uint4*)src;
    uint4* d = (uint4*)dst;
    size_t sstr = src_stride >> 3;
    #pragma unroll
    for (int idx = tid; idx < 2048; idx += 256) {
        int r = idx >> 4, c = idx & 15;
        d[r * 17 + c] = s[(size_t)r * sstr + c];
    }
}

// ======== scores: HMMA GEMM + fused exp + per-CTA column partial sums =======
// Stores E = exp(scale * q.kpv) as bf16 in S, and per-mtile column sums.
extern "C" __global__ void __launch_bounds__(256)
scores_hmma_kernel(const __nv_bfloat16* __restrict__ qbf,
                   const __nv_bfloat16* __restrict__ kbf,
                   __nv_bfloat16* __restrict__ S,
                   float* __restrict__ psum)
{
    __nv_bfloat16* qs = (__nv_bfloat16*)hx_smem;
    __nv_bfloat16* ks = (__nv_bfloat16*)(hx_smem + TILE_BYTES);
    float* colsum = (float*)(hx_smem + 2 * TILE_BYTES);  // [2][128]
    int tid = threadIdx.x, lane = tid & 31, w = tid >> 5;
    int wm = w >> 2, wn = w & 3;
    int n0 = blockIdx.x * 128, mt = blockIdx.y, b = blockIdx.z;
    int m0 = mt * 128;

    load_tile(qs, qbf + (size_t)(b * MM + m0) * 128, 128, tid);
    load_tile(ks, kbf + (size_t)(b * NN + n0) * 128, 128, tid);
    __syncthreads();

    uint32_t a_base = abase(smem_to_u32(qs), wm, lane);
    uint32_t b_base = bbase(smem_to_u32(ks), wn, lane);

    float acc[4][4][4];
    ZERO_ACC(acc);
    hmma_pass(a_base, b_base, acc);

    // exp epilogue + store + local column sums
    float lsum[8];
    #pragma unroll
    for (int t = 0; t < 8; ++t) lsum[t] = 0.f;

    size_t Sbase = (size_t)b * MM * NN;
    #pragma unroll
    for (int i = 0; i < 4; ++i) {
        int row = m0 + wm * 64 + i * 16 + (lane >> 2);
        #pragma unroll
        for (int jt = 0; jt < 4; ++jt) {
            int col = n0 + wn * 32 + jt * 8 + (lane & 3) * 2;
            float e0 = __expf(acc[i][jt][0] * SCALE);
            float e1 = __expf(acc[i][jt][1] * SCALE);
            float e2 = __expf(acc[i][jt][2] * SCALE);
            float e3 = __expf(acc[i][jt][3] * SCALE);
            __nv_bfloat162 p0 = __float22bfloat162_rn(make_float2(e0, e1));
            __nv_bfloat162 p1 = __float22bfloat162_rn(make_float2(e2, e3));
            *(uint32_t*)(S + Sbase + (size_t)row * NN + col)       = *(uint32_t*)&p0;
            *(uint32_t*)(S + Sbase + (size_t)(row + 8) * NN + col) = *(uint32_t*)&p1;
            // sum what we actually stored (bf16-rounded) for exact normalization
            float2 q0 = __bfloat1622float2(p0), q1 = __bfloat1622float2(p1);
            lsum[jt * 2]     += q0.x + q1.x;
            lsum[jt * 2 + 1] += q0.y + q1.y;
        }
    }
    // reduce over the 8 row-lanes (same lane&3 group)
    #pragma unroll
    for (int off = 16; off >= 4; off >>= 1)
        #pragma unroll
        for (int t = 0; t < 8; ++t)
            lsum[t] += __shfl_down_sync(0xffffffffu, lsum[t], off);
    if (lane < 4) {
        #pragma unroll
        for (int jt = 0; jt < 4; ++jt) {
            colsum[wm * 128 + wn * 32 + jt * 8 + lane * 2]     = lsum[jt * 2];
            colsum[wm * 128 + wn * 32 + jt * 8 + lane * 2 + 1] = lsum[jt * 2 + 1];
        }
    }
    __syncthreads();
    if (tid < 128)
        psum[((size_t)mt * BB + b) * NN + n0 + tid] =
            colsum[tid] + colsum[128 + tid];
}

// ============ column-sum reduce: cinv = 1 / sum_mt(psum) ====================
extern "C" __global__ void __launch_bounds__(256)
colsum_inv_kernel(const float* __restrict__ psum, float* __restrict__ cinv)
{
    int idx = blockIdx.x * 256 + threadIdx.x;   // over BB*NN
    float s = 0.f;
    #pragma unroll
    for (int mt = 0; mt < MTILES; ++mt)
        s += psum[(size_t)mt * BB * NN + idx];
    cinv[idx] = 1.f / s;
}

// ============== out: warp HMMA, split-K over n, fp32 partials ===============
extern "C" __global__ void __launch_bounds__(256)
out_hmma_kernel(const __nv_bfloat16* __restrict__ S,
                const __nv_bfloat16* __restrict__ vT,
                const float* __restrict__ cinv,
                float* __restrict__ part)
{
    __nv_bfloat16* Ps = (__nv_bfloat16*)hx_smem;
    __nv_bfloat16* Vs = (__nv_bfloat16*)(hx_smem + TILE_BYTES);
    float* ci = (float*)(hx_smem + 2 * TILE_BYTES);   // [128]
    int tid = threadIdx.x, lane = tid & 31, w = tid >> 5;
    int wm = w >> 2, wn = w & 3;
    int m0 = blockIdx.x * 128, seg = blockIdx.y, b = blockIdx.z;
    int nbase = seg * (NN / SEGS);

    uint32_t a_base = abase(smem_to_u32(Ps), wm, lane);
    uint32_t b_base = bbase(smem_to_u32(Vs), wn, lane);

    const __nv_bfloat16* Sb = S  + ((size_t)b * MM + m0) * NN;
    const __nv_bfloat16* Vb = vT + (size_t)b * DD * NN;

    float acc[4][4][4];
    ZERO_ACC(acc);

    #pragma unroll 1
    for (int ch = 0; ch < NN / SEGS / 128; ++ch) {
        int n0 = nbase + ch * 128;
        if (tid < 128) ci[tid] = cinv[b * NN + n0 + tid];
        __syncthreads();

        // P tile = E * cinv (bf16); no exp needed
        #pragma unroll
        for (int idx = tid; idx < 2048; idx += 256) {
            int r = idx >> 4, c = idx & 15;
            uint4 sv = *(const uint4*)(Sb + (size_t)r * NN + n0 + c * 8);
            __nv_bfloat162* sp = (__nv_bfloat162*)&sv;
            uint32_t pk[4];
            #pragma unroll
            for (int j = 0; j < 4; ++j) {
                float2 ff = __bfloat1622float2(sp[j]);
                int cc = c * 8 + 2 * j;
                ff.x *= ci[cc]; ff.y *= ci[cc + 1];
                __nv_bfloat162 p = __float22bfloat162_rn(ff);
                pk[j] = *(uint32_t*)&p;
            }
            ((uint4*)Ps)[r * 17 + c] = *(uint4*)pk;
        }
        load_tile(Vs, Vb + n0, NN, tid);
        __syncthreads();

        hmma_pass(a_base, b_base, acc);
        __syncthreads();
    }

    float* dst = part + ((size_t)(seg * BB + b) * MM) * DD;
    #pragma unroll
    for (int i = 0; i < 4; ++i) {
        int row = m0 + wm * 64 + i * 16 + (lane >> 2);
        #pragma unroll
        for (int jt = 0; jt < 4; ++jt) {
            int col = wn * 32 + jt * 8 + (lane & 3) * 2;
            *(float2*)(dst + (size_t)row * DD + col) =
                make_float2(acc[i][jt][0], acc[i][jt][1]);
            *(float2*)(dst + (size_t)(row + 8) * DD + col) =
                make_float2(acc[i][jt][2], acc[i][jt][3]);
        }
    }
}

// ===================== final reduce: out = vfeat + sum(partials) ============
extern "C" __global__ void __launch_bounds__(256)
reduce_kernel(const float* __restrict__ part, const float* __restrict__ vfeat,
              float* __restrict__ out)
{
    const size_t T = (size_t)BB * MM * DD;
    size_t i = ((size_t)blockIdx.x * 256 + threadIdx.x) * 4;
    float4 a = *(const float4*)(vfeat + i);
    #pragma unroll
    for (int s = 0; s < SEGS; ++s) {
        float4 p = *(const float4*)(part + s * T + i);
        a.x += p.x; a.y += p.y; a.z += p.z; a.w += p.w;
    }
    *(float4*)(out + i) = a;
}

// ---------------------------------------------------------------------------
extern "C" void kernel_launch(void* const* d_in, const int* in_sizes, int n_in,
                              void* d_out, int out_size)
{
    const float* p_xyz  = (const float*)d_in[0];
    const float* v_xyz  = (const float*)d_in[1];
    const float* p_feat = (const float*)d_in[2];
    const float* v_feat = (const float*)d_in[3];
    const float* aW1 = (const float*)d_in[4];
    const float* ab1 = (const float*)d_in[5];
    const float* aW2 = (const float*)d_in[6];
    const float* ab2 = (const float*)d_in[7];
    const float* bW1 = (const float*)d_in[8];
    const float* bb1 = (const float*)d_in[9];
    const float* bW2 = (const float*)d_in[10];
    const float* bb2 = (const float*)d_in[11];
    const float* oW1 = (const float*)d_in[12];
    const float* ob1 = (const float*)d_in[13];
    const float* oW2 = (const float*)d_in[14];
    const float* ob2 = (const float*)d_in[15];
    const float* dW1 = (const float*)d_in[16];
    const float* db1 = (const float*)d_in[17];
    const float* dW2 = (const float*)d_in[18];
    const float* db2 = (const float*)d_in[19];
    float* out = (float*)d_out;

    void *S_p, *kpvb_p, *vT_p, *qb_p, *psum_p, *cinv_p, *part_p;
    cudaGetSymbolAddress(&S_p,    g_S);
    cudaGetSymbolAddress(&kpvb_p, g_kpvb);
    cudaGetSymbolAddress(&vT_p,   g_vT);
    cudaGetSymbolAddress(&qb_p,   g_qb);
    cudaGetSymbolAddress(&psum_p, g_psum);
    cudaGetSymbolAddress(&cinv_p, g_cinv);
    cudaGetSymbolAddress(&part_p, g_part);

    const int PTS_SMEM = 4 * TILE_BYTES + 2048 + 1536;
    cudaFuncSetAttribute(points_mlp_hmma,
                         cudaFuncAttributeMaxDynamicSharedMemorySize, PTS_SMEM);
    cudaFuncSetAttribute(q_mlp_hmma,
                         cudaFuncAttributeMaxDynamicSharedMemorySize, 3 * TILE_BYTES);
    cudaFuncSetAttribute(scores_hmma_kernel,
                         cudaFuncAttributeMaxDynamicSharedMemorySize, 2 * TILE_BYTES + 1024);
    cudaFuncSetAttribute(out_hmma_kernel,
                         cudaFuncAttributeMaxDynamicSharedMemorySize, 2 * TILE_BYTES + 1024);

    // kpv bf16 + vT bf16 (beta + delta + omega, HMMA)
    points_mlp_hmma<<<256, 256, PTS_SMEM>>>(
        p_feat, p_xyz, v_xyz,
        bW1, bb1, bW2, bb2, oW1, ob1, oW2, ob2, dW1, db1, dW2, db2,
        (__nv_bfloat16*)kpvb_p, (__nv_bfloat16*)vT_p);
    // q bf16 (alpha, HMMA)
    q_mlp_hmma<<<64, 256, 3 * TILE_BYTES>>>(
        v_feat, aW1, ab1, aW2, ab2, (__nv_bfloat16*)qb_p);
    // E = exp(scale * q @ kpv^T) + per-mtile column sums (fused)
    scores_hmma_kernel<<<dim3(128, MTILES, 2), 256, 2 * TILE_BYTES + 1024>>>(
        (const __nv_bfloat16*)qb_p, (const __nv_bfloat16*)kpvb_p,
        (__nv_bfloat16*)S_p, (float*)psum_p);
    // cinv = 1 / column sums
    colsum_inv_kernel<<<BB * NN / 256, 256>>>((const float*)psum_p,
                                              (float*)cinv_p);
    // partials = (E * cinv) @ v   (HMMA, split-K = SEGS)
    out_hmma_kernel<<<dim3(32, SEGS, 2), 256, 2 * TILE_BYTES + 1024>>>(
        (const __nv_bfloat16*)S_p, (const __nv_bfloat16*)vT_p,
        (const float*)cinv_p, (float*)part_p);
    // out = v_features + sum(partials)
    reduce_kernel<<<1024, 256>>>((const float*)part_p, v_feat, out);
}